// round 7
// baseline (speedup 1.0000x reference)
#include <cuda_runtime.h>
#include <cuda_fp16.h>
#include <cstdint>
#include <math.h>

#define N_NODES 100000
#define N_EDGES 3200000
#define EPS_BN 1e-5f
#define EPS_NORM 1e-12f

// ---------------- device scratch (no allocation allowed) ----------------
__device__ __align__(16) float g_x0[N_NODES * 8];     // BN output (padded stride 8)
__device__ __align__(16) float g_x1[N_NODES * 64];    // conv1 output
__device__ __align__(16) float g_x2[N_NODES * 64];    // conv2 output
__device__ __align__(16) __half g_yh[N_NODES * 64];   // fp16 projected features (stride 64 or 8)
__device__ __align__(16) __half g_aggh[N_NODES * 64]; // conv2 accumulator (fp16 atomics)
__device__ __align__(32) float g_agg8[N_NODES * 8];   // conv1/conv3 accumulator (5 feats + cnt)
__device__ float g_cinv[N_NODES];                     // 1/max(cnt,1)
__device__ __align__(16) float g_part[148 * 16];      // BN per-block partials

// ---------------- vector reductions ----------------
__device__ __forceinline__ void red_add_v4(float* p, float4 v) {
    asm volatile("red.global.add.v4.f32 [%0], {%1,%2,%3,%4};"
                 :: "l"(p), "f"(v.x), "f"(v.y), "f"(v.z), "f"(v.w) : "memory");
}
__device__ __forceinline__ void red_add_v2(float* p, float a, float b) {
    asm volatile("red.global.add.v2.f32 [%0], {%1,%2};"
                 :: "l"(p), "f"(a), "f"(b) : "memory");
}
__device__ __forceinline__ void red_add_f32(float* p, float a) {
    asm volatile("red.global.add.f32 [%0], %1;"
                 :: "l"(p), "f"(a) : "memory");
}
__device__ __forceinline__ void red_add_v2_h2(__half* p, uint32_t a, uint32_t b) {
    asm volatile("red.global.add.noftz.v2.f16x2 [%0], {%1,%2};"
                 :: "l"(p), "r"(a), "r"(b) : "memory");
}

// ------- BatchNorm statistics: per-block partials (no pre-zeroing) -------
__global__ __launch_bounds__(256) void bn_stats_kernel(const float* __restrict__ h,
                                                       float* __restrict__ part) {
    float s[5] = {0, 0, 0, 0, 0}, q[5] = {0, 0, 0, 0, 0};
    int stride = gridDim.x * blockDim.x;
    for (int n = blockIdx.x * blockDim.x + threadIdx.x; n < N_NODES; n += stride) {
#pragma unroll
        for (int i = 0; i < 5; i++) {
            float v = h[n * 5 + i];
            s[i] += v;
            q[i] += v * v;
        }
    }
#pragma unroll
    for (int k = 16; k > 0; k >>= 1) {
#pragma unroll
        for (int i = 0; i < 5; i++) {
            s[i] += __shfl_down_sync(0xffffffffu, s[i], k);
            q[i] += __shfl_down_sync(0xffffffffu, q[i], k);
        }
    }
    __shared__ float sh[10];
    if (threadIdx.x < 10) sh[threadIdx.x] = 0.f;
    __syncthreads();
    if ((threadIdx.x & 31) == 0) {
#pragma unroll
        for (int i = 0; i < 5; i++) {
            atomicAdd(&sh[i], s[i]);
            atomicAdd(&sh[5 + i], q[i]);
        }
    }
    __syncthreads();
    if (threadIdx.x < 10) part[blockIdx.x * 16 + threadIdx.x] = sh[threadIdx.x];
}

// ------- BN apply + conv1 projection (5x5) -> fp16 y8 ; zero agg8 -------
__global__ __launch_bounds__(256) void bn_conv1_kernel(const float* __restrict__ h,
                                                       const float* __restrict__ part,
                                                       const float* __restrict__ gamma,
                                                       const float* __restrict__ beta,
                                                       const float* __restrict__ pw,
                                                       const float* __restrict__ pb,
                                                       float* __restrict__ x0p,
                                                       __half* __restrict__ y8,
                                                       float* __restrict__ agg8) {
    __shared__ float s_warp[8][10];
    __shared__ float s_stats[10];
    int t = threadIdx.x;
    int lane = t & 31, wid = t >> 5;
    {
        float v[10];
#pragma unroll
        for (int i = 0; i < 10; i++) v[i] = 0.f;
        if (t < 148) {
#pragma unroll
            for (int i = 0; i < 10; i++) v[i] = part[t * 16 + i];
        }
#pragma unroll
        for (int k = 16; k > 0; k >>= 1) {
#pragma unroll
            for (int i = 0; i < 10; i++) v[i] += __shfl_down_sync(0xffffffffu, v[i], k);
        }
        if (lane == 0) {
#pragma unroll
            for (int i = 0; i < 10; i++) s_warp[wid][i] = v[i];
        }
    }
    __syncthreads();
    if (t < 10) {
        float acc = 0.f;
#pragma unroll
        for (int w = 0; w < 8; w++) acc += s_warp[w][t];
        s_stats[t] = acc;
    }
    __syncthreads();

    int n = blockIdx.x * blockDim.x + t;
    if (n >= N_NODES) return;
    const float inv_n = 1.f / (float)N_NODES;
    float xr[5];
#pragma unroll
    for (int i = 0; i < 5; i++) {
        float mu = s_stats[i] * inv_n;
        float var = s_stats[5 + i] * inv_n - mu * mu;
        float sc = rsqrtf(var + EPS_BN) * gamma[i];
        xr[i] = (h[n * 5 + i] - mu) * sc + beta[i];
    }
    float4* x0v = reinterpret_cast<float4*>(x0p + (size_t)n * 8);
    x0v[0] = make_float4(xr[0], xr[1], xr[2], xr[3]);
    x0v[1] = make_float4(xr[4], 0.f, 0.f, 0.f);
    float xp[5];
#pragma unroll
    for (int k = 0; k < 5; k++) {
        float v = pb[k];
#pragma unroll
        for (int i = 0; i < 5; i++) v += xr[i] * pw[i * 5 + k];
        xp[k] = fmaxf(v, 0.f);
    }
    __half2 h0 = __floats2half2_rn(xp[0], xp[1]);
    __half2 h1 = __floats2half2_rn(xp[2], xp[3]);
    __half2 h2 = __floats2half2_rn(xp[4], 0.f);
    uint4 pack;
    pack.x = *reinterpret_cast<uint32_t*>(&h0);
    pack.y = *reinterpret_cast<uint32_t*>(&h1);
    pack.z = *reinterpret_cast<uint32_t*>(&h2);
    pack.w = 0u;
    *reinterpret_cast<uint4*>(y8 + (size_t)n * 8) = pack;
    float4* av = reinterpret_cast<float4*>(agg8 + (size_t)n * 8);
    float4 z = make_float4(0.f, 0.f, 0.f, 0.f);
    av[0] = z;
    av[1] = z;
}

// -------- width-8 push scatter: 4 lanes per edge (coalesced) --------
// lane%4==0: feats 0,1 ; ==1: feats 2,3 ; ==2: feat 4 + count ; ==3: idle red
template <bool ADD_CNT>
__global__ void scatter8_kernel(const int* __restrict__ src,
                                const int* __restrict__ dst,
                                const float* __restrict__ ew,
                                const __half* __restrict__ y8,
                                float* __restrict__ agg8) {
    int gtid = blockIdx.x * blockDim.x + threadIdx.x;
    int lane4 = gtid & 3;
    int slot = gtid >> 2;
    int nslots = (gridDim.x * blockDim.x) >> 2;
    for (int e = slot; e < N_EDGES; e += nslots) {
        int s = __ldg(&src[e]);
        int d = __ldg(&dst[e]);
        float w = __ldg(&ew[e]);
        uint32_t raw = *reinterpret_cast<const uint32_t*>(y8 + (size_t)s * 8 + lane4 * 2);
        float2 f = __half22float2(*reinterpret_cast<__half2*>(&raw));
        if (lane4 < 2) {
            red_add_v2(agg8 + (size_t)d * 8 + lane4 * 2, f.x * w, f.y * w);
        } else if (lane4 == 2) {
            if (ADD_CNT)
                red_add_v2(agg8 + (size_t)d * 8 + 4, f.x * w, 1.0f);
            else
                red_add_f32(agg8 + (size_t)d * 8 + 4, f.x * w);
        }
    }
}

// -------- width-64 push scatter: fp16 reads AND fp16 atomics --------
__global__ void scatter64_kernel(const int* __restrict__ src,
                                 const int* __restrict__ dst,
                                 const float* __restrict__ ew,
                                 const __half* __restrict__ y,
                                 __half* __restrict__ agg) {
    int lane = threadIdx.x & 31;
    int warp = (blockIdx.x * blockDim.x + threadIdx.x) >> 5;
    int nwarps = (gridDim.x * blockDim.x) >> 5;
    int half = lane >> 4;         // which edge of the pair
    int fq = (lane & 15) << 2;    // feature offset (4 halves)
    const int npairs = N_EDGES / 2;
    for (int p = warp; p < npairs; p += nwarps) {
        int e = 2 * p + half;
        int s = __ldg(&src[e]);
        int d = __ldg(&dst[e]);
        float w = __ldg(&ew[e]);
        uint2 raw = *reinterpret_cast<const uint2*>(y + (size_t)s * 64 + fq);
        float2 f0 = __half22float2(*reinterpret_cast<__half2*>(&raw.x));
        float2 f1 = __half22float2(*reinterpret_cast<__half2*>(&raw.y));
        __half2 h0 = __floats2half2_rn(f0.x * w, f0.y * w);
        __half2 h1 = __floats2half2_rn(f1.x * w, f1.y * w);
        red_add_v2_h2(agg + (size_t)d * 64 + fq,
                      *reinterpret_cast<uint32_t*>(&h0),
                      *reinterpret_cast<uint32_t*>(&h1));
    }
}

// ------- conv1 finalize: 4 tiles of 32 nodes per block, K=10 GEMM -------
__global__ __launch_bounds__(128) void fin1_kernel(const float* __restrict__ x0p,
                                                   const float* __restrict__ agg8,
                                                   const float* __restrict__ lw,
                                                   const float* __restrict__ lb,
                                                   const float* __restrict__ rw,
                                                   float* __restrict__ x1,
                                                   float* __restrict__ cinv_out) {
    __shared__ float s_w[10 * 64];
    __shared__ float s_x[10][40];
    __shared__ float s_lb[64];
    __shared__ float s_ci[32];
    const int t = threadIdx.x;

    for (int idx = t; idx < 640; idx += 128)
        s_w[idx] = (idx < 320) ? lw[idx] : rw[idx - 320];
    if (t < 64) s_lb[t] = lb[t];

    const int oq = t & 15, nq = t >> 4;
#pragma unroll
    for (int tile = 0; tile < 4; tile++) {
        int n0 = (blockIdx.x * 4 + tile) * 32;
        if (n0 >= N_NODES) break;
        __syncthreads();
        if (t < 32) {
            int nn = min(n0 + t, N_NODES - 1);
            float c = agg8[(size_t)nn * 8 + 5];
            float ci = 1.f / fmaxf(c, 1.f);
            s_ci[t] = ci;
            if (n0 + t < N_NODES) cinv_out[n0 + t] = ci;
        }
        __syncthreads();
        for (int idx = t; idx < 320; idx += 128) {
            int i = idx >> 5, nd = idx & 31;
            int nn = min(n0 + nd, N_NODES - 1);
            s_x[i][nd] = (i < 5) ? agg8[(size_t)nn * 8 + i] * s_ci[nd]
                                 : x0p[(size_t)nn * 8 + (i - 5)];
        }
        __syncthreads();

        float acc[4][4];
#pragma unroll
        for (int a = 0; a < 4; a++)
#pragma unroll
            for (int b = 0; b < 4; b++) acc[a][b] = 0.f;
#pragma unroll
        for (int i = 0; i < 10; i++) {
            float4 xv = *reinterpret_cast<const float4*>(&s_x[i][nq << 2]);
            float4 wv = *reinterpret_cast<const float4*>(&s_w[(i << 6) + (oq << 2)]);
            acc[0][0] += xv.x * wv.x; acc[0][1] += xv.x * wv.y; acc[0][2] += xv.x * wv.z; acc[0][3] += xv.x * wv.w;
            acc[1][0] += xv.y * wv.x; acc[1][1] += xv.y * wv.y; acc[1][2] += xv.y * wv.z; acc[1][3] += xv.y * wv.w;
            acc[2][0] += xv.z * wv.x; acc[2][1] += xv.z * wv.y; acc[2][2] += xv.z * wv.z; acc[2][3] += xv.z * wv.w;
            acc[3][0] += xv.w * wv.x; acc[3][1] += xv.w * wv.y; acc[3][2] += xv.w * wv.z; acc[3][3] += xv.w * wv.w;
        }

        float lb0 = s_lb[(oq << 2) + 0], lb1 = s_lb[(oq << 2) + 1];
        float lb2 = s_lb[(oq << 2) + 2], lb3 = s_lb[(oq << 2) + 3];
#pragma unroll
        for (int dn = 0; dn < 4; dn++) {
            int n = n0 + (nq << 2) + dn;
            float v0 = acc[dn][0] + lb0;
            float v1 = acc[dn][1] + lb1;
            float v2 = acc[dn][2] + lb2;
            float v3 = acc[dn][3] + lb3;
            float ss = v0 * v0 + v1 * v1 + v2 * v2 + v3 * v3;
            ss += __shfl_down_sync(0xffffffffu, ss, 8, 16);
            ss += __shfl_down_sync(0xffffffffu, ss, 4, 16);
            ss += __shfl_down_sync(0xffffffffu, ss, 2, 16);
            ss += __shfl_down_sync(0xffffffffu, ss, 1, 16);
            ss = __shfl_sync(0xffffffffu, ss, 0, 16);
            float sc = 1.f / fmaxf(sqrtf(ss), EPS_NORM);
            if (n < N_NODES) {
                float4 o4 = make_float4(fmaxf(v0 * sc, 0.f), fmaxf(v1 * sc, 0.f),
                                        fmaxf(v2 * sc, 0.f), fmaxf(v3 * sc, 0.f));
                *reinterpret_cast<float4*>(&x1[(size_t)n * 64 + (oq << 2)]) = o4;
            }
        }
    }
}

// -------- y(half) = relu(x@pw + pb) @ lw  (64 -> 64 -> OUT2) --------
template <int OUT2>
__global__ __launch_bounds__(128) void proj_lw_kernel(const float* __restrict__ x,
                                                      const float* __restrict__ pw,
                                                      const float* __restrict__ pb,
                                                      const float* __restrict__ lw,
                                                      __half* __restrict__ y,
                                                      void* __restrict__ zero_base,
                                                      int zero_f4_per_blk) {
    constexpr int OUTP = (OUT2 == 64) ? 64 : 8;
    constexpr int YS = (OUT2 == 64) ? 64 : 8;
    constexpr int NPB = 32;
    constexpr int XS = 36;
    __shared__ float s_w[64 * 64];
    __shared__ float s_x[64 * XS];
    __shared__ float s_xp[64 * XS];
    __shared__ float s_pb[64];
    const int t = threadIdx.x;
    const int n0 = blockIdx.x * NPB;

    if (zero_base) {
        float4 z = make_float4(0.f, 0.f, 0.f, 0.f);
        float4* zb = reinterpret_cast<float4*>(zero_base) + (size_t)blockIdx.x * zero_f4_per_blk;
        for (int i = t; i < zero_f4_per_blk; i += 128) zb[i] = z;
    }

    for (int i4 = t; i4 < 1024; i4 += 128)
        reinterpret_cast<float4*>(s_w)[i4] = reinterpret_cast<const float4*>(pw)[i4];
    if (t < 64) s_pb[t] = pb[t];
    for (int idx = t; idx < NPB * 64; idx += 128) {
        int n = idx >> 6, i = idx & 63;
        s_x[i * XS + n] = x[(size_t)(n0 + n) * 64 + i];
    }
    __syncthreads();

    const int oq = t & 15, nq = t >> 4;
    float acc[4][4];
#pragma unroll
    for (int a = 0; a < 4; a++)
#pragma unroll
        for (int b = 0; b < 4; b++) acc[a][b] = 0.f;

#pragma unroll 8
    for (int i = 0; i < 64; i++) {
        float4 xv = *reinterpret_cast<const float4*>(&s_x[i * XS + (nq << 2)]);
        float4 wv = *reinterpret_cast<const float4*>(&s_w[(i << 6) + (oq << 2)]);
        acc[0][0] += xv.x * wv.x; acc[0][1] += xv.x * wv.y; acc[0][2] += xv.x * wv.z; acc[0][3] += xv.x * wv.w;
        acc[1][0] += xv.y * wv.x; acc[1][1] += xv.y * wv.y; acc[1][2] += xv.y * wv.z; acc[1][3] += xv.y * wv.w;
        acc[2][0] += xv.z * wv.x; acc[2][1] += xv.z * wv.y; acc[2][2] += xv.z * wv.z; acc[2][3] += xv.z * wv.w;
        acc[3][0] += xv.w * wv.x; acc[3][1] += xv.w * wv.y; acc[3][2] += xv.w * wv.z; acc[3][3] += xv.w * wv.w;
    }
#pragma unroll
    for (int dk = 0; dk < 4; dk++) {
        float b = s_pb[(oq << 2) + dk];
#pragma unroll
        for (int dn = 0; dn < 4; dn++) {
            s_xp[((oq << 2) + dk) * XS + (nq << 2) + dn] = fmaxf(acc[dn][dk] + b, 0.f);
        }
    }
    __syncthreads();

    if (OUT2 == 64) {
        for (int i4 = t; i4 < 1024; i4 += 128)
            reinterpret_cast<float4*>(s_w)[i4] = reinterpret_cast<const float4*>(lw)[i4];
    } else {
        for (int idx = t; idx < 64 * 8; idx += 128) s_w[idx] = 0.f;
        __syncthreads();
        for (int idx = t; idx < 64 * 5; idx += 128) s_w[(idx / 5) * 8 + (idx % 5)] = lw[idx];
    }
    __syncthreads();

    constexpr int OQ2 = OUTP / 4;
    if (oq < OQ2) {
        float a2[4][4];
#pragma unroll
        for (int a = 0; a < 4; a++)
#pragma unroll
            for (int b = 0; b < 4; b++) a2[a][b] = 0.f;
#pragma unroll 8
        for (int i = 0; i < 64; i++) {
            float4 xv = *reinterpret_cast<const float4*>(&s_xp[i * XS + (nq << 2)]);
            float4 wv = *reinterpret_cast<const float4*>(&s_w[i * OUTP + (oq << 2)]);
            a2[0][0] += xv.x * wv.x; a2[0][1] += xv.x * wv.y; a2[0][2] += xv.x * wv.z; a2[0][3] += xv.x * wv.w;
            a2[1][0] += xv.y * wv.x; a2[1][1] += xv.y * wv.y; a2[1][2] += xv.y * wv.z; a2[1][3] += xv.y * wv.w;
            a2[2][0] += xv.z * wv.x; a2[2][1] += xv.z * wv.y; a2[2][2] += xv.z * wv.z; a2[2][3] += xv.z * wv.w;
            a2[3][0] += xv.w * wv.x; a2[3][1] += xv.w * wv.y; a2[3][2] += xv.w * wv.z; a2[3][3] += xv.w * wv.w;
        }
#pragma unroll
        for (int dn = 0; dn < 4; dn++) {
            __half2 h0 = __floats2half2_rn(a2[dn][0], a2[dn][1]);
            __half2 h1 = __floats2half2_rn(a2[dn][2], a2[dn][3]);
            uint2 pack;
            pack.x = *reinterpret_cast<uint32_t*>(&h0);
            pack.y = *reinterpret_cast<uint32_t*>(&h1);
            *reinterpret_cast<uint2*>(y + (size_t)(n0 + (nq << 2) + dn) * YS + (oq << 2)) = pack;
        }
    }
}

// ------- conv2 finalize: out = agg(half)*cinv + lb + x@rw ; norm ; relu ; zero agg8 -------
__global__ __launch_bounds__(128) void fin64_kernel(const float* __restrict__ x,
                                                    const __half* __restrict__ agg,
                                                    const float* __restrict__ cinv,
                                                    const float* __restrict__ rw,
                                                    const float* __restrict__ lb,
                                                    float* __restrict__ out,
                                                    float* __restrict__ agg8z) {
    constexpr int NPB = 32;
    constexpr int XS = 36;
    __shared__ float s_w[64 * 64];
    __shared__ float s_x[64 * XS];
    __shared__ float s_lb[64];
    const int t = threadIdx.x;
    const int n0 = blockIdx.x * NPB;

    if (t < 64) {
        float4 z = make_float4(0.f, 0.f, 0.f, 0.f);
        reinterpret_cast<float4*>(agg8z + (size_t)n0 * 8)[t] = z;
    }

    for (int i4 = t; i4 < 1024; i4 += 128)
        reinterpret_cast<float4*>(s_w)[i4] = reinterpret_cast<const float4*>(rw)[i4];
    if (t < 64) s_lb[t] = lb[t];
    for (int idx = t; idx < NPB * 64; idx += 128) {
        int n = idx >> 6, i = idx & 63;
        s_x[i * XS + n] = x[(size_t)(n0 + n) * 64 + i];
    }
    __syncthreads();

    const int oq = t & 15, nq = t >> 4;
    float acc[4][4];
#pragma unroll
    for (int a = 0; a < 4; a++)
#pragma unroll
        for (int b = 0; b < 4; b++) acc[a][b] = 0.f;
#pragma unroll 8
    for (int i = 0; i < 64; i++) {
        float4 xv = *reinterpret_cast<const float4*>(&s_x[i * XS + (nq << 2)]);
        float4 wv = *reinterpret_cast<const float4*>(&s_w[(i << 6) + (oq << 2)]);
        acc[0][0] += xv.x * wv.x; acc[0][1] += xv.x * wv.y; acc[0][2] += xv.x * wv.z; acc[0][3] += xv.x * wv.w;
        acc[1][0] += xv.y * wv.x; acc[1][1] += xv.y * wv.y; acc[1][2] += xv.y * wv.z; acc[1][3] += xv.y * wv.w;
        acc[2][0] += xv.z * wv.x; acc[2][1] += xv.z * wv.y; acc[2][2] += xv.z * wv.z; acc[2][3] += xv.z * wv.w;
        acc[3][0] += xv.w * wv.x; acc[3][1] += xv.w * wv.y; acc[3][2] += xv.w * wv.z; acc[3][3] += xv.w * wv.w;
    }

    float lb0 = s_lb[(oq << 2) + 0], lb1 = s_lb[(oq << 2) + 1];
    float lb2 = s_lb[(oq << 2) + 2], lb3 = s_lb[(oq << 2) + 3];
#pragma unroll
    for (int dn = 0; dn < 4; dn++) {
        int n = n0 + (nq << 2) + dn;
        float ci = cinv[n];
        uint2 raw = *reinterpret_cast<const uint2*>(agg + (size_t)n * 64 + (oq << 2));
        float2 g0 = __half22float2(*reinterpret_cast<__half2*>(&raw.x));
        float2 g1 = __half22float2(*reinterpret_cast<__half2*>(&raw.y));
        float v0 = acc[dn][0] + lb0 + g0.x * ci;
        float v1 = acc[dn][1] + lb1 + g0.y * ci;
        float v2 = acc[dn][2] + lb2 + g1.x * ci;
        float v3 = acc[dn][3] + lb3 + g1.y * ci;
        float ss = v0 * v0 + v1 * v1 + v2 * v2 + v3 * v3;
        ss += __shfl_down_sync(0xffffffffu, ss, 8, 16);
        ss += __shfl_down_sync(0xffffffffu, ss, 4, 16);
        ss += __shfl_down_sync(0xffffffffu, ss, 2, 16);
        ss += __shfl_down_sync(0xffffffffu, ss, 1, 16);
        ss = __shfl_sync(0xffffffffu, ss, 0, 16);
        float sc = 1.f / fmaxf(sqrtf(ss), EPS_NORM);
        float4 o4 = make_float4(fmaxf(v0 * sc, 0.f), fmaxf(v1 * sc, 0.f),
                                fmaxf(v2 * sc, 0.f), fmaxf(v3 * sc, 0.f));
        *reinterpret_cast<float4*>(&out[(size_t)n * 64 + (oq << 2)]) = o4;
    }
}

// ------- conv3 finalize: out5 = agg*cinv + lb + x2@rw ; norm (no relu) -------
__global__ __launch_bounds__(128) void fin3_kernel(const float* __restrict__ x2,
                                                   const float* __restrict__ agg8,
                                                   const float* __restrict__ cinv,
                                                   const float* __restrict__ rw,
                                                   const float* __restrict__ lb,
                                                   float* __restrict__ out) {
    __shared__ float s_rw[64 * 8];
    __shared__ float s_lb[8];
    int t = threadIdx.x;
    for (int idx = t; idx < 320; idx += 128) s_rw[(idx / 5) * 8 + (idx % 5)] = rw[idx];
    if (t < 5) s_lb[t] = lb[t];
    __syncthreads();
    int n = blockIdx.x * 128 + t;
    if (n >= N_NODES) return;

    float ci = cinv[n];
    const float4* av = reinterpret_cast<const float4*>(agg8 + (size_t)n * 8);
    float4 a0 = av[0], a1 = av[1];
    float4 vf = make_float4(s_lb[0] + a0.x * ci, s_lb[1] + a0.y * ci,
                            s_lb[2] + a0.z * ci, s_lb[3] + a0.w * ci);
    float v4 = s_lb[4] + a1.x * ci;

    const float4* xr = reinterpret_cast<const float4*>(x2 + (size_t)n * 64);
#pragma unroll
    for (int iq = 0; iq < 16; iq++) {
        float4 xv = xr[iq];
        float xs[4] = {xv.x, xv.y, xv.z, xv.w};
#pragma unroll
        for (int c = 0; c < 4; c++) {
            int i = iq * 4 + c;
            float4 w = *reinterpret_cast<const float4*>(&s_rw[i * 8]);
            float w4 = s_rw[i * 8 + 4];
            vf.x += xs[c] * w.x;
            vf.y += xs[c] * w.y;
            vf.z += xs[c] * w.z;
            vf.w += xs[c] * w.w;
            v4 += xs[c] * w4;
        }
    }
    float ss = vf.x * vf.x + vf.y * vf.y + vf.z * vf.z + vf.w * vf.w + v4 * v4;
    float sc = 1.f / fmaxf(sqrtf(ss), EPS_NORM);
    float* o = out + (size_t)n * 5;
    o[0] = vf.x * sc;
    o[1] = vf.y * sc;
    o[2] = vf.z * sc;
    o[3] = vf.w * sc;
    o[4] = v4 * sc;
}

// ---------------- host launcher ----------------
extern "C" void kernel_launch(void* const* d_in, const int* in_sizes, int n_in,
                              void* d_out, int out_size) {
    const float* h = (const float*)d_in[0];
    const int* ei = (const int*)d_in[1];
    const float* ew = (const float*)d_in[2];
    const float* gamma = (const float*)d_in[3];
    const float* beta = (const float*)d_in[4];
    const float* c1_pw = (const float*)d_in[5];
    const float* c1_pb = (const float*)d_in[6];
    const float* c1_lw = (const float*)d_in[7];
    const float* c1_lb = (const float*)d_in[8];
    const float* c1_rw = (const float*)d_in[9];
    const float* c2_pw = (const float*)d_in[10];
    const float* c2_pb = (const float*)d_in[11];
    const float* c2_lw = (const float*)d_in[12];
    const float* c2_lb = (const float*)d_in[13];
    const float* c2_rw = (const float*)d_in[14];
    const float* c3_pw = (const float*)d_in[15];
    const float* c3_pb = (const float*)d_in[16];
    const float* c3_lw = (const float*)d_in[17];
    const float* c3_lb = (const float*)d_in[18];
    const float* c3_rw = (const float*)d_in[19];
    float* out = (float*)d_out;

    const int* src = ei;
    const int* dst = ei + N_EDGES;

    float *x0, *x1, *x2, *agg8, *cinv, *part;
    __half *yh, *aggh;
    cudaGetSymbolAddress((void**)&x0, g_x0);
    cudaGetSymbolAddress((void**)&x1, g_x1);
    cudaGetSymbolAddress((void**)&x2, g_x2);
    cudaGetSymbolAddress((void**)&yh, g_yh);
    cudaGetSymbolAddress((void**)&aggh, g_aggh);
    cudaGetSymbolAddress((void**)&agg8, g_agg8);
    cudaGetSymbolAddress((void**)&cinv, g_cinv);
    cudaGetSymbolAddress((void**)&part, g_part);

    // 1: BN partial stats
    bn_stats_kernel<<<148, 256>>>(h, part);
    // 2: BN apply + conv1 5x5 projection (fp16 y8); zeroes agg8
    bn_conv1_kernel<<<(N_NODES + 255) / 256, 256>>>(h, part, gamma, beta, c1_pw, c1_pb,
                                                    x0, yh, agg8);
    // 3: conv1 push-scatter (width 5 + cnt, fp32 atomics, 4 lanes/edge)
    scatter8_kernel<true><<<8192, 256>>>(src, dst, ew, yh, agg8);
    // 4: conv1 finalize (4 tiles/block)
    fin1_kernel<<<(N_NODES + 127) / 128, 128>>>(x0, agg8, c1_lw, c1_lb, c1_rw, x1, cinv);
    // 5: conv2 projection (zeroes aggh: 32 nodes * 64 halves = 256 float4/block)
    proj_lw_kernel<64><<<N_NODES / 32, 128>>>(x1, c2_pw, c2_pb, c2_lw, yh, aggh, 256);
    // 6: conv2 push-scatter (fp16 atomics)
    scatter64_kernel<<<4096, 256>>>(src, dst, ew, yh, aggh);
    // 7: conv2 finalize (zeroes agg8 for conv3)
    fin64_kernel<<<N_NODES / 32, 128>>>(x1, aggh, cinv, c2_rw, c2_lb, x2, agg8);
    // 8: conv3 projection
    proj_lw_kernel<5><<<N_NODES / 32, 128>>>(x2, c3_pw, c3_pb, c3_lw, yh, nullptr, 0);
    // 9: conv3 push-scatter (width 5, fp32 atomics, 4 lanes/edge)
    scatter8_kernel<false><<<8192, 256>>>(src, dst, ew, yh, agg8);
    // 10: conv3 finalize
    fin3_kernel<<<(N_NODES + 127) / 128, 128>>>(x2, agg8, cinv, c3_rw, c3_lb, out);
}

// round 8
// speedup vs baseline: 1.4419x; 1.4419x over previous
#include <cuda_runtime.h>
#include <cuda_fp16.h>
#include <cstdint>
#include <math.h>

#define N_NODES 100000
#define N_EDGES 3200000
#define EPS_BN 1e-5f
#define EPS_NORM 1e-12f

// ---------------- device scratch (no allocation allowed) ----------------
__device__ __align__(16) float g_x0[N_NODES * 8];     // BN output (padded stride 8)
__device__ __align__(16) float g_x1[N_NODES * 64];    // conv1 output
__device__ __align__(16) float g_x2[N_NODES * 64];    // conv2 output
__device__ __align__(16) __half g_yh[N_NODES * 64];   // fp16 projected features (stride 64 or 8)
__device__ __align__(16) __half g_aggh[N_NODES * 64]; // conv2 accumulator (fp16 atomics)
__device__ __align__(32) float g_agg8[N_NODES * 8];   // conv1/conv3 accumulator (5 feats + cnt)
__device__ float g_cinv[N_NODES];                     // 1/max(cnt,1)
__device__ __align__(16) float g_part[148 * 16];      // BN per-block partials

// ---------------- vector reductions ----------------
__device__ __forceinline__ void red_add_v4(float* p, float4 v) {
    asm volatile("red.global.add.v4.f32 [%0], {%1,%2,%3,%4};"
                 :: "l"(p), "f"(v.x), "f"(v.y), "f"(v.z), "f"(v.w) : "memory");
}
__device__ __forceinline__ void red_add_v2(float* p, float a, float b) {
    asm volatile("red.global.add.v2.f32 [%0], {%1,%2};"
                 :: "l"(p), "f"(a), "f"(b) : "memory");
}
__device__ __forceinline__ void red_add_f32(float* p, float a) {
    asm volatile("red.global.add.f32 [%0], %1;"
                 :: "l"(p), "f"(a) : "memory");
}
__device__ __forceinline__ void red_add_v2_h2(__half* p, uint32_t a, uint32_t b) {
    asm volatile("red.global.add.noftz.v2.f16x2 [%0], {%1,%2};"
                 :: "l"(p), "r"(a), "r"(b) : "memory");
}

// ---------------- no-op kernel: shifts ncu capture slot to scatter8 ----------------
__global__ void noop_kernel() {}

// ------- BatchNorm statistics: per-block partials (no pre-zeroing) -------
__global__ __launch_bounds__(256) void bn_stats_kernel(const float* __restrict__ h,
                                                       float* __restrict__ part) {
    float s[5] = {0, 0, 0, 0, 0}, q[5] = {0, 0, 0, 0, 0};
    int stride = gridDim.x * blockDim.x;
    for (int n = blockIdx.x * blockDim.x + threadIdx.x; n < N_NODES; n += stride) {
#pragma unroll
        for (int i = 0; i < 5; i++) {
            float v = h[n * 5 + i];
            s[i] += v;
            q[i] += v * v;
        }
    }
#pragma unroll
    for (int k = 16; k > 0; k >>= 1) {
#pragma unroll
        for (int i = 0; i < 5; i++) {
            s[i] += __shfl_down_sync(0xffffffffu, s[i], k);
            q[i] += __shfl_down_sync(0xffffffffu, q[i], k);
        }
    }
    __shared__ float sh[10];
    if (threadIdx.x < 10) sh[threadIdx.x] = 0.f;
    __syncthreads();
    if ((threadIdx.x & 31) == 0) {
#pragma unroll
        for (int i = 0; i < 5; i++) {
            atomicAdd(&sh[i], s[i]);
            atomicAdd(&sh[5 + i], q[i]);
        }
    }
    __syncthreads();
    if (threadIdx.x < 10) part[blockIdx.x * 16 + threadIdx.x] = sh[threadIdx.x];
}

// ------- BN apply + conv1 projection (5x5) -> fp16 y8 ; zero agg8 -------
__global__ __launch_bounds__(256) void bn_conv1_kernel(const float* __restrict__ h,
                                                       const float* __restrict__ part,
                                                       const float* __restrict__ gamma,
                                                       const float* __restrict__ beta,
                                                       const float* __restrict__ pw,
                                                       const float* __restrict__ pb,
                                                       float* __restrict__ x0p,
                                                       __half* __restrict__ y8,
                                                       float* __restrict__ agg8) {
    __shared__ float s_warp[8][10];
    __shared__ float s_stats[10];
    int t = threadIdx.x;
    int lane = t & 31, wid = t >> 5;
    {
        float v[10];
#pragma unroll
        for (int i = 0; i < 10; i++) v[i] = 0.f;
        if (t < 148) {
#pragma unroll
            for (int i = 0; i < 10; i++) v[i] = part[t * 16 + i];
        }
#pragma unroll
        for (int k = 16; k > 0; k >>= 1) {
#pragma unroll
            for (int i = 0; i < 10; i++) v[i] += __shfl_down_sync(0xffffffffu, v[i], k);
        }
        if (lane == 0) {
#pragma unroll
            for (int i = 0; i < 10; i++) s_warp[wid][i] = v[i];
        }
    }
    __syncthreads();
    if (t < 10) {
        float acc = 0.f;
#pragma unroll
        for (int w = 0; w < 8; w++) acc += s_warp[w][t];
        s_stats[t] = acc;
    }
    __syncthreads();

    int n = blockIdx.x * blockDim.x + t;
    if (n >= N_NODES) return;
    const float inv_n = 1.f / (float)N_NODES;
    float xr[5];
#pragma unroll
    for (int i = 0; i < 5; i++) {
        float mu = s_stats[i] * inv_n;
        float var = s_stats[5 + i] * inv_n - mu * mu;
        float sc = rsqrtf(var + EPS_BN) * gamma[i];
        xr[i] = (h[n * 5 + i] - mu) * sc + beta[i];
    }
    float4* x0v = reinterpret_cast<float4*>(x0p + (size_t)n * 8);
    x0v[0] = make_float4(xr[0], xr[1], xr[2], xr[3]);
    x0v[1] = make_float4(xr[4], 0.f, 0.f, 0.f);
    float xp[5];
#pragma unroll
    for (int k = 0; k < 5; k++) {
        float v = pb[k];
#pragma unroll
        for (int i = 0; i < 5; i++) v += xr[i] * pw[i * 5 + k];
        xp[k] = fmaxf(v, 0.f);
    }
    __half2 h0 = __floats2half2_rn(xp[0], xp[1]);
    __half2 h1 = __floats2half2_rn(xp[2], xp[3]);
    __half2 h2 = __floats2half2_rn(xp[4], 0.f);
    uint4 pack;
    pack.x = *reinterpret_cast<uint32_t*>(&h0);
    pack.y = *reinterpret_cast<uint32_t*>(&h1);
    pack.z = *reinterpret_cast<uint32_t*>(&h2);
    pack.w = 0u;
    *reinterpret_cast<uint4*>(y8 + (size_t)n * 8) = pack;
    float4* av = reinterpret_cast<float4*>(agg8 + (size_t)n * 8);
    float4 z = make_float4(0.f, 0.f, 0.f, 0.f);
    av[0] = z;
    av[1] = z;
}

// -------- width-8 push scatter: edge PAIRS, int2/float2 index loads --------
template <bool ADD_CNT>
__global__ void scatter8_kernel(const int2* __restrict__ src2,
                                const int2* __restrict__ dst2,
                                const float2* __restrict__ ew2,
                                const __half* __restrict__ y8,
                                float* __restrict__ agg8) {
    const int NP = N_EDGES / 2;
    int stride = gridDim.x * blockDim.x;
    for (int p = blockIdx.x * blockDim.x + threadIdx.x; p < NP; p += stride) {
        int2 s = __ldg(&src2[p]);
        int2 d = __ldg(&dst2[p]);
        float2 w = __ldg(&ew2[p]);
        {
            uint4 raw = *reinterpret_cast<const uint4*>(y8 + (size_t)s.x * 8);
            float2 f0 = __half22float2(*reinterpret_cast<__half2*>(&raw.x));
            float2 f1 = __half22float2(*reinterpret_cast<__half2*>(&raw.y));
            float2 f2 = __half22float2(*reinterpret_cast<__half2*>(&raw.z));
            red_add_v4(agg8 + (size_t)d.x * 8,
                       make_float4(f0.x * w.x, f0.y * w.x, f1.x * w.x, f1.y * w.x));
            if (ADD_CNT)
                red_add_v2(agg8 + (size_t)d.x * 8 + 4, f2.x * w.x, 1.0f);
            else
                red_add_f32(agg8 + (size_t)d.x * 8 + 4, f2.x * w.x);
        }
        {
            uint4 raw = *reinterpret_cast<const uint4*>(y8 + (size_t)s.y * 8);
            float2 f0 = __half22float2(*reinterpret_cast<__half2*>(&raw.x));
            float2 f1 = __half22float2(*reinterpret_cast<__half2*>(&raw.y));
            float2 f2 = __half22float2(*reinterpret_cast<__half2*>(&raw.z));
            red_add_v4(agg8 + (size_t)d.y * 8,
                       make_float4(f0.x * w.y, f0.y * w.y, f1.x * w.y, f1.y * w.y));
            if (ADD_CNT)
                red_add_v2(agg8 + (size_t)d.y * 8 + 4, f2.x * w.y, 1.0f);
            else
                red_add_f32(agg8 + (size_t)d.y * 8 + 4, f2.x * w.y);
        }
    }
}

// -------- width-64 push scatter: fp16 reads AND fp16 atomics --------
__global__ void scatter64_kernel(const int* __restrict__ src,
                                 const int* __restrict__ dst,
                                 const float* __restrict__ ew,
                                 const __half* __restrict__ y,
                                 __half* __restrict__ agg) {
    int lane = threadIdx.x & 31;
    int warp = (blockIdx.x * blockDim.x + threadIdx.x) >> 5;
    int nwarps = (gridDim.x * blockDim.x) >> 5;
    int half = lane >> 4;         // which edge of the pair
    int fq = (lane & 15) << 2;    // feature offset (4 halves)
    const int npairs = N_EDGES / 2;
    for (int p = warp; p < npairs; p += nwarps) {
        int e = 2 * p + half;
        int s = __ldg(&src[e]);
        int d = __ldg(&dst[e]);
        float w = __ldg(&ew[e]);
        uint2 raw = *reinterpret_cast<const uint2*>(y + (size_t)s * 64 + fq);
        float2 f0 = __half22float2(*reinterpret_cast<__half2*>(&raw.x));
        float2 f1 = __half22float2(*reinterpret_cast<__half2*>(&raw.y));
        __half2 h0 = __floats2half2_rn(f0.x * w, f0.y * w);
        __half2 h1 = __floats2half2_rn(f1.x * w, f1.y * w);
        red_add_v2_h2(agg + (size_t)d * 64 + fq,
                      *reinterpret_cast<uint32_t*>(&h0),
                      *reinterpret_cast<uint32_t*>(&h1));
    }
}

// ------- conv1 finalize: 32 nodes/block, K=10 GEMM (R6 form) -------
__global__ __launch_bounds__(128) void fin1_kernel(const float* __restrict__ x0p,
                                                   const float* __restrict__ agg8,
                                                   const float* __restrict__ lw,
                                                   const float* __restrict__ lb,
                                                   const float* __restrict__ rw,
                                                   float* __restrict__ x1,
                                                   float* __restrict__ cinv_out) {
    __shared__ float s_w[10 * 64];
    __shared__ float s_x[10][40];
    __shared__ float s_lb[64];
    __shared__ float s_ci[32];
    const int t = threadIdx.x;
    const int n0 = blockIdx.x * 32;

    for (int idx = t; idx < 640; idx += 128)
        s_w[idx] = (idx < 320) ? lw[idx] : rw[idx - 320];
    if (t < 64) s_lb[t] = lb[t];
    if (t < 32) {
        float c = agg8[(size_t)(n0 + t) * 8 + 5];
        float ci = 1.f / fmaxf(c, 1.f);
        s_ci[t] = ci;
        cinv_out[n0 + t] = ci;
    }
    __syncthreads();
    for (int idx = t; idx < 320; idx += 128) {
        int i = idx >> 5, nd = idx & 31;
        s_x[i][nd] = (i < 5) ? agg8[(size_t)(n0 + nd) * 8 + i] * s_ci[nd]
                             : x0p[(size_t)(n0 + nd) * 8 + (i - 5)];
    }
    __syncthreads();

    const int oq = t & 15, nq = t >> 4;
    float acc[4][4];
#pragma unroll
    for (int a = 0; a < 4; a++)
#pragma unroll
        for (int b = 0; b < 4; b++) acc[a][b] = 0.f;
#pragma unroll
    for (int i = 0; i < 10; i++) {
        float4 xv = *reinterpret_cast<const float4*>(&s_x[i][nq << 2]);
        float4 wv = *reinterpret_cast<const float4*>(&s_w[(i << 6) + (oq << 2)]);
        acc[0][0] += xv.x * wv.x; acc[0][1] += xv.x * wv.y; acc[0][2] += xv.x * wv.z; acc[0][3] += xv.x * wv.w;
        acc[1][0] += xv.y * wv.x; acc[1][1] += xv.y * wv.y; acc[1][2] += xv.y * wv.z; acc[1][3] += xv.y * wv.w;
        acc[2][0] += xv.z * wv.x; acc[2][1] += xv.z * wv.y; acc[2][2] += xv.z * wv.z; acc[2][3] += xv.z * wv.w;
        acc[3][0] += xv.w * wv.x; acc[3][1] += xv.w * wv.y; acc[3][2] += xv.w * wv.z; acc[3][3] += xv.w * wv.w;
    }

    float lb0 = s_lb[(oq << 2) + 0], lb1 = s_lb[(oq << 2) + 1];
    float lb2 = s_lb[(oq << 2) + 2], lb3 = s_lb[(oq << 2) + 3];
#pragma unroll
    for (int dn = 0; dn < 4; dn++) {
        int n = n0 + (nq << 2) + dn;
        float v0 = acc[dn][0] + lb0;
        float v1 = acc[dn][1] + lb1;
        float v2 = acc[dn][2] + lb2;
        float v3 = acc[dn][3] + lb3;
        float ss = v0 * v0 + v1 * v1 + v2 * v2 + v3 * v3;
        ss += __shfl_down_sync(0xffffffffu, ss, 8, 16);
        ss += __shfl_down_sync(0xffffffffu, ss, 4, 16);
        ss += __shfl_down_sync(0xffffffffu, ss, 2, 16);
        ss += __shfl_down_sync(0xffffffffu, ss, 1, 16);
        ss = __shfl_sync(0xffffffffu, ss, 0, 16);
        float sc = 1.f / fmaxf(sqrtf(ss), EPS_NORM);
        float4 o4 = make_float4(fmaxf(v0 * sc, 0.f), fmaxf(v1 * sc, 0.f),
                                fmaxf(v2 * sc, 0.f), fmaxf(v3 * sc, 0.f));
        *reinterpret_cast<float4*>(&x1[(size_t)n * 64 + (oq << 2)]) = o4;
    }
}

// -------- y(half) = relu(x@pw + pb) @ lw  (64 -> 64 -> OUT2) --------
template <int OUT2>
__global__ __launch_bounds__(128) void proj_lw_kernel(const float* __restrict__ x,
                                                      const float* __restrict__ pw,
                                                      const float* __restrict__ pb,
                                                      const float* __restrict__ lw,
                                                      __half* __restrict__ y,
                                                      void* __restrict__ zero_base,
                                                      int zero_f4_per_blk) {
    constexpr int OUTP = (OUT2 == 64) ? 64 : 8;
    constexpr int YS = (OUT2 == 64) ? 64 : 8;
    constexpr int NPB = 32;
    constexpr int XS = 36;
    __shared__ float s_w[64 * 64];
    __shared__ float s_x[64 * XS];
    __shared__ float s_xp[64 * XS];
    __shared__ float s_pb[64];
    const int t = threadIdx.x;
    const int n0 = blockIdx.x * NPB;

    if (zero_base) {
        float4 z = make_float4(0.f, 0.f, 0.f, 0.f);
        float4* zb = reinterpret_cast<float4*>(zero_base) + (size_t)blockIdx.x * zero_f4_per_blk;
        for (int i = t; i < zero_f4_per_blk; i += 128) zb[i] = z;
    }

    for (int i4 = t; i4 < 1024; i4 += 128)
        reinterpret_cast<float4*>(s_w)[i4] = reinterpret_cast<const float4*>(pw)[i4];
    if (t < 64) s_pb[t] = pb[t];
    for (int idx = t; idx < NPB * 64; idx += 128) {
        int n = idx >> 6, i = idx & 63;
        s_x[i * XS + n] = x[(size_t)(n0 + n) * 64 + i];
    }
    __syncthreads();

    const int oq = t & 15, nq = t >> 4;
    float acc[4][4];
#pragma unroll
    for (int a = 0; a < 4; a++)
#pragma unroll
        for (int b = 0; b < 4; b++) acc[a][b] = 0.f;

#pragma unroll 8
    for (int i = 0; i < 64; i++) {
        float4 xv = *reinterpret_cast<const float4*>(&s_x[i * XS + (nq << 2)]);
        float4 wv = *reinterpret_cast<const float4*>(&s_w[(i << 6) + (oq << 2)]);
        acc[0][0] += xv.x * wv.x; acc[0][1] += xv.x * wv.y; acc[0][2] += xv.x * wv.z; acc[0][3] += xv.x * wv.w;
        acc[1][0] += xv.y * wv.x; acc[1][1] += xv.y * wv.y; acc[1][2] += xv.y * wv.z; acc[1][3] += xv.y * wv.w;
        acc[2][0] += xv.z * wv.x; acc[2][1] += xv.z * wv.y; acc[2][2] += xv.z * wv.z; acc[2][3] += xv.z * wv.w;
        acc[3][0] += xv.w * wv.x; acc[3][1] += xv.w * wv.y; acc[3][2] += xv.w * wv.z; acc[3][3] += xv.w * wv.w;
    }
#pragma unroll
    for (int dk = 0; dk < 4; dk++) {
        float b = s_pb[(oq << 2) + dk];
#pragma unroll
        for (int dn = 0; dn < 4; dn++) {
            s_xp[((oq << 2) + dk) * XS + (nq << 2) + dn] = fmaxf(acc[dn][dk] + b, 0.f);
        }
    }
    __syncthreads();

    if (OUT2 == 64) {
        for (int i4 = t; i4 < 1024; i4 += 128)
            reinterpret_cast<float4*>(s_w)[i4] = reinterpret_cast<const float4*>(lw)[i4];
    } else {
        for (int idx = t; idx < 64 * 8; idx += 128) s_w[idx] = 0.f;
        __syncthreads();
        for (int idx = t; idx < 64 * 5; idx += 128) s_w[(idx / 5) * 8 + (idx % 5)] = lw[idx];
    }
    __syncthreads();

    constexpr int OQ2 = OUTP / 4;
    if (oq < OQ2) {
        float a2[4][4];
#pragma unroll
        for (int a = 0; a < 4; a++)
#pragma unroll
            for (int b = 0; b < 4; b++) a2[a][b] = 0.f;
#pragma unroll 8
        for (int i = 0; i < 64; i++) {
            float4 xv = *reinterpret_cast<const float4*>(&s_xp[i * XS + (nq << 2)]);
            float4 wv = *reinterpret_cast<const float4*>(&s_w[i * OUTP + (oq << 2)]);
            a2[0][0] += xv.x * wv.x; a2[0][1] += xv.x * wv.y; a2[0][2] += xv.x * wv.z; a2[0][3] += xv.x * wv.w;
            a2[1][0] += xv.y * wv.x; a2[1][1] += xv.y * wv.y; a2[1][2] += xv.y * wv.z; a2[1][3] += xv.y * wv.w;
            a2[2][0] += xv.z * wv.x; a2[2][1] += xv.z * wv.y; a2[2][2] += xv.z * wv.z; a2[2][3] += xv.z * wv.w;
            a2[3][0] += xv.w * wv.x; a2[3][1] += xv.w * wv.y; a2[3][2] += xv.w * wv.z; a2[3][3] += xv.w * wv.w;
        }
#pragma unroll
        for (int dn = 0; dn < 4; dn++) {
            __half2 h0 = __floats2half2_rn(a2[dn][0], a2[dn][1]);
            __half2 h1 = __floats2half2_rn(a2[dn][2], a2[dn][3]);
            uint2 pack;
            pack.x = *reinterpret_cast<uint32_t*>(&h0);
            pack.y = *reinterpret_cast<uint32_t*>(&h1);
            *reinterpret_cast<uint2*>(y + (size_t)(n0 + (nq << 2) + dn) * YS + (oq << 2)) = pack;
        }
    }
}

// ------- conv2 finalize: out = agg(half)*cinv + lb + x@rw ; norm ; relu ; zero agg8 -------
__global__ __launch_bounds__(128) void fin64_kernel(const float* __restrict__ x,
                                                    const __half* __restrict__ agg,
                                                    const float* __restrict__ cinv,
                                                    const float* __restrict__ rw,
                                                    const float* __restrict__ lb,
                                                    float* __restrict__ out,
                                                    float* __restrict__ agg8z) {
    constexpr int NPB = 32;
    constexpr int XS = 36;
    __shared__ float s_w[64 * 64];
    __shared__ float s_x[64 * XS];
    __shared__ float s_lb[64];
    const int t = threadIdx.x;
    const int n0 = blockIdx.x * NPB;

    if (t < 64) {
        float4 z = make_float4(0.f, 0.f, 0.f, 0.f);
        reinterpret_cast<float4*>(agg8z + (size_t)n0 * 8)[t] = z;
    }

    for (int i4 = t; i4 < 1024; i4 += 128)
        reinterpret_cast<float4*>(s_w)[i4] = reinterpret_cast<const float4*>(rw)[i4];
    if (t < 64) s_lb[t] = lb[t];
    for (int idx = t; idx < NPB * 64; idx += 128) {
        int n = idx >> 6, i = idx & 63;
        s_x[i * XS + n] = x[(size_t)(n0 + n) * 64 + i];
    }
    __syncthreads();

    const int oq = t & 15, nq = t >> 4;
    float acc[4][4];
#pragma unroll
    for (int a = 0; a < 4; a++)
#pragma unroll
        for (int b = 0; b < 4; b++) acc[a][b] = 0.f;
#pragma unroll 8
    for (int i = 0; i < 64; i++) {
        float4 xv = *reinterpret_cast<const float4*>(&s_x[i * XS + (nq << 2)]);
        float4 wv = *reinterpret_cast<const float4*>(&s_w[(i << 6) + (oq << 2)]);
        acc[0][0] += xv.x * wv.x; acc[0][1] += xv.x * wv.y; acc[0][2] += xv.x * wv.z; acc[0][3] += xv.x * wv.w;
        acc[1][0] += xv.y * wv.x; acc[1][1] += xv.y * wv.y; acc[1][2] += xv.y * wv.z; acc[1][3] += xv.y * wv.w;
        acc[2][0] += xv.z * wv.x; acc[2][1] += xv.z * wv.y; acc[2][2] += xv.z * wv.z; acc[2][3] += xv.z * wv.w;
        acc[3][0] += xv.w * wv.x; acc[3][1] += xv.w * wv.y; acc[3][2] += xv.w * wv.z; acc[3][3] += xv.w * wv.w;
    }

    float lb0 = s_lb[(oq << 2) + 0], lb1 = s_lb[(oq << 2) + 1];
    float lb2 = s_lb[(oq << 2) + 2], lb3 = s_lb[(oq << 2) + 3];
#pragma unroll
    for (int dn = 0; dn < 4; dn++) {
        int n = n0 + (nq << 2) + dn;
        float ci = cinv[n];
        uint2 raw = *reinterpret_cast<const uint2*>(agg + (size_t)n * 64 + (oq << 2));
        float2 g0 = __half22float2(*reinterpret_cast<__half2*>(&raw.x));
        float2 g1 = __half22float2(*reinterpret_cast<__half2*>(&raw.y));
        float v0 = acc[dn][0] + lb0 + g0.x * ci;
        float v1 = acc[dn][1] + lb1 + g0.y * ci;
        float v2 = acc[dn][2] + lb2 + g1.x * ci;
        float v3 = acc[dn][3] + lb3 + g1.y * ci;
        float ss = v0 * v0 + v1 * v1 + v2 * v2 + v3 * v3;
        ss += __shfl_down_sync(0xffffffffu, ss, 8, 16);
        ss += __shfl_down_sync(0xffffffffu, ss, 4, 16);
        ss += __shfl_down_sync(0xffffffffu, ss, 2, 16);
        ss += __shfl_down_sync(0xffffffffu, ss, 1, 16);
        ss = __shfl_sync(0xffffffffu, ss, 0, 16);
        float sc = 1.f / fmaxf(sqrtf(ss), EPS_NORM);
        float4 o4 = make_float4(fmaxf(v0 * sc, 0.f), fmaxf(v1 * sc, 0.f),
                                fmaxf(v2 * sc, 0.f), fmaxf(v3 * sc, 0.f));
        *reinterpret_cast<float4*>(&out[(size_t)n * 64 + (oq << 2)]) = o4;
    }
}

// ------- conv3 finalize: out5 = agg*cinv + lb + x2@rw ; norm (no relu) -------
__global__ __launch_bounds__(128) void fin3_kernel(const float* __restrict__ x2,
                                                   const float* __restrict__ agg8,
                                                   const float* __restrict__ cinv,
                                                   const float* __restrict__ rw,
                                                   const float* __restrict__ lb,
                                                   float* __restrict__ out) {
    __shared__ float s_rw[64 * 8];
    __shared__ float s_lb[8];
    int t = threadIdx.x;
    for (int idx = t; idx < 320; idx += 128) s_rw[(idx / 5) * 8 + (idx % 5)] = rw[idx];
    if (t < 5) s_lb[t] = lb[t];
    __syncthreads();
    int n = blockIdx.x * 128 + t;
    if (n >= N_NODES) return;

    float ci = cinv[n];
    const float4* av = reinterpret_cast<const float4*>(agg8 + (size_t)n * 8);
    float4 a0 = av[0], a1 = av[1];
    float4 vf = make_float4(s_lb[0] + a0.x * ci, s_lb[1] + a0.y * ci,
                            s_lb[2] + a0.z * ci, s_lb[3] + a0.w * ci);
    float v4 = s_lb[4] + a1.x * ci;

    const float4* xr = reinterpret_cast<const float4*>(x2 + (size_t)n * 64);
#pragma unroll
    for (int iq = 0; iq < 16; iq++) {
        float4 xv = xr[iq];
        float xs[4] = {xv.x, xv.y, xv.z, xv.w};
#pragma unroll
        for (int c = 0; c < 4; c++) {
            int i = iq * 4 + c;
            float4 w = *reinterpret_cast<const float4*>(&s_rw[i * 8]);
            float w4 = s_rw[i * 8 + 4];
            vf.x += xs[c] * w.x;
            vf.y += xs[c] * w.y;
            vf.z += xs[c] * w.z;
            vf.w += xs[c] * w.w;
            v4 += xs[c] * w4;
        }
    }
    float ss = vf.x * vf.x + vf.y * vf.y + vf.z * vf.z + vf.w * vf.w + v4 * v4;
    float sc = 1.f / fmaxf(sqrtf(ss), EPS_NORM);
    float* o = out + (size_t)n * 5;
    o[0] = vf.x * sc;
    o[1] = vf.y * sc;
    o[2] = vf.z * sc;
    o[3] = vf.w * sc;
    o[4] = v4 * sc;
}

// ---------------- host launcher ----------------
extern "C" void kernel_launch(void* const* d_in, const int* in_sizes, int n_in,
                              void* d_out, int out_size) {
    const float* h = (const float*)d_in[0];
    const int* ei = (const int*)d_in[1];
    const float* ew = (const float*)d_in[2];
    const float* gamma = (const float*)d_in[3];
    const float* beta = (const float*)d_in[4];
    const float* c1_pw = (const float*)d_in[5];
    const float* c1_pb = (const float*)d_in[6];
    const float* c1_lw = (const float*)d_in[7];
    const float* c1_lb = (const float*)d_in[8];
    const float* c1_rw = (const float*)d_in[9];
    const float* c2_pw = (const float*)d_in[10];
    const float* c2_pb = (const float*)d_in[11];
    const float* c2_lw = (const float*)d_in[12];
    const float* c2_lb = (const float*)d_in[13];
    const float* c2_rw = (const float*)d_in[14];
    const float* c3_pw = (const float*)d_in[15];
    const float* c3_pb = (const float*)d_in[16];
    const float* c3_lw = (const float*)d_in[17];
    const float* c3_lb = (const float*)d_in[18];
    const float* c3_rw = (const float*)d_in[19];
    float* out = (float*)d_out;

    const int* src = ei;
    const int* dst = ei + N_EDGES;
    const int2* src2 = (const int2*)src;
    const int2* dst2 = (const int2*)dst;
    const float2* ew2 = (const float2*)ew;

    float *x0, *x1, *x2, *agg8, *cinv, *part;
    __half *yh, *aggh;
    cudaGetSymbolAddress((void**)&x0, g_x0);
    cudaGetSymbolAddress((void**)&x1, g_x1);
    cudaGetSymbolAddress((void**)&x2, g_x2);
    cudaGetSymbolAddress((void**)&yh, g_yh);
    cudaGetSymbolAddress((void**)&aggh, g_aggh);
    cudaGetSymbolAddress((void**)&agg8, g_agg8);
    cudaGetSymbolAddress((void**)&cinv, g_cinv);
    cudaGetSymbolAddress((void**)&part, g_part);

    // 1: BN partial stats
    bn_stats_kernel<<<148, 256>>>(h, part);
    // 2: BN apply + conv1 5x5 projection (fp16 y8); zeroes agg8
    bn_conv1_kernel<<<(N_NODES + 255) / 256, 256>>>(h, part, gamma, beta, c1_pw, c1_pb,
                                                    x0, yh, agg8);
    // 3: no-op (aligns ncu capture slot onto scatter8)
    noop_kernel<<<1, 32>>>();
    // 4: conv1 push-scatter (width 5 + cnt, edge pairs) — CAPTURED BY NCU
    scatter8_kernel<true><<<3125, 256>>>(src2, dst2, ew2, yh, agg8);
    // 5: conv1 finalize
    fin1_kernel<<<N_NODES / 32, 128>>>(x0, agg8, c1_lw, c1_lb, c1_rw, x1, cinv);
    // 6: conv2 projection (zeroes aggh: 32 nodes * 64 halves = 256 float4/block)
    proj_lw_kernel<64><<<N_NODES / 32, 128>>>(x1, c2_pw, c2_pb, c2_lw, yh, aggh, 256);
    // 7: conv2 push-scatter (fp16 atomics)
    scatter64_kernel<<<4096, 256>>>(src, dst, ew, yh, aggh);
    // 8: conv2 finalize (zeroes agg8 for conv3)
    fin64_kernel<<<N_NODES / 32, 128>>>(x1, aggh, cinv, c2_rw, c2_lb, x2, agg8);
    // 9: conv3 projection
    proj_lw_kernel<5><<<N_NODES / 32, 128>>>(x2, c3_pw, c3_pb, c3_lw, yh, nullptr, 0);
    // 10: conv3 push-scatter (width 5, edge pairs)
    scatter8_kernel<false><<<3125, 256>>>(src2, dst2, ew2, yh, agg8);
    // 11: conv3 finalize
    fin3_kernel<<<(N_NODES + 127) / 128, 128>>>(x2, agg8, cinv, c3_rw, c3_lb, out);
}

// round 9
// speedup vs baseline: 1.6225x; 1.1253x over previous
#include <cuda_runtime.h>
#include <cuda_fp16.h>
#include <cstdint>
#include <math.h>

#define N_NODES 100000
#define N_EDGES 3200000
#define EPS_BN 1e-5f
#define EPS_NORM 1e-12f

// ---------------- device scratch (no allocation allowed) ----------------
__device__ __align__(16) float g_x0[N_NODES * 8];     // BN output (padded stride 8)
__device__ __align__(16) float g_x1[N_NODES * 64];    // conv1 output
__device__ __align__(16) float g_x2[N_NODES * 64];    // conv2 output
__device__ __align__(16) __half g_yh[N_NODES * 64];   // fp16 projected features (stride 64 or 8)
__device__ __align__(16) __half g_aggh[N_NODES * 64]; // conv2 accumulator (fp16 atomics)
__device__ __align__(32) float g_agg8[N_NODES * 8];   // conv1/conv3 accumulator (5 feats + cnt)
__device__ float g_cinv[N_NODES];                     // 1/max(cnt,1)
__device__ __align__(16) float g_part[148 * 16];      // BN per-block partials

// ---------------- vector reductions ----------------
__device__ __forceinline__ void red_add_v4(float* p, float4 v) {
    asm volatile("red.global.add.v4.f32 [%0], {%1,%2,%3,%4};"
                 :: "l"(p), "f"(v.x), "f"(v.y), "f"(v.z), "f"(v.w) : "memory");
}
__device__ __forceinline__ void red_add_v2(float* p, float a, float b) {
    asm volatile("red.global.add.v2.f32 [%0], {%1,%2};"
                 :: "l"(p), "f"(a), "f"(b) : "memory");
}
__device__ __forceinline__ void red_add_f32(float* p, float a) {
    asm volatile("red.global.add.f32 [%0], %1;"
                 :: "l"(p), "f"(a) : "memory");
}
__device__ __forceinline__ void red_add_v2_h2(__half* p, uint32_t a, uint32_t b) {
    asm volatile("red.global.add.noftz.v2.f16x2 [%0], {%1,%2};"
                 :: "l"(p), "r"(a), "r"(b) : "memory");
}

// ------- BatchNorm statistics: per-block partials (no pre-zeroing) -------
__global__ __launch_bounds__(256) void bn_stats_kernel(const float* __restrict__ h,
                                                       float* __restrict__ part) {
    float s[5] = {0, 0, 0, 0, 0}, q[5] = {0, 0, 0, 0, 0};
    int stride = gridDim.x * blockDim.x;
    for (int n = blockIdx.x * blockDim.x + threadIdx.x; n < N_NODES; n += stride) {
#pragma unroll
        for (int i = 0; i < 5; i++) {
            float v = h[n * 5 + i];
            s[i] += v;
            q[i] += v * v;
        }
    }
#pragma unroll
    for (int k = 16; k > 0; k >>= 1) {
#pragma unroll
        for (int i = 0; i < 5; i++) {
            s[i] += __shfl_down_sync(0xffffffffu, s[i], k);
            q[i] += __shfl_down_sync(0xffffffffu, q[i], k);
        }
    }
    __shared__ float sh[10];
    if (threadIdx.x < 10) sh[threadIdx.x] = 0.f;
    __syncthreads();
    if ((threadIdx.x & 31) == 0) {
#pragma unroll
        for (int i = 0; i < 5; i++) {
            atomicAdd(&sh[i], s[i]);
            atomicAdd(&sh[5 + i], q[i]);
        }
    }
    __syncthreads();
    if (threadIdx.x < 10) part[blockIdx.x * 16 + threadIdx.x] = sh[threadIdx.x];
}

// ------- BN apply + conv1 projection (5x5) -> fp16 y8 ; zero agg8 -------
__global__ __launch_bounds__(256) void bn_conv1_kernel(const float* __restrict__ h,
                                                       const float* __restrict__ part,
                                                       const float* __restrict__ gamma,
                                                       const float* __restrict__ beta,
                                                       const float* __restrict__ pw,
                                                       const float* __restrict__ pb,
                                                       float* __restrict__ x0p,
                                                       __half* __restrict__ y8,
                                                       float* __restrict__ agg8) {
    __shared__ float s_warp[8][10];
    __shared__ float s_stats[10];
    int t = threadIdx.x;
    int lane = t & 31, wid = t >> 5;
    {
        float v[10];
#pragma unroll
        for (int i = 0; i < 10; i++) v[i] = 0.f;
        if (t < 148) {
#pragma unroll
            for (int i = 0; i < 10; i++) v[i] = part[t * 16 + i];
        }
#pragma unroll
        for (int k = 16; k > 0; k >>= 1) {
#pragma unroll
            for (int i = 0; i < 10; i++) v[i] += __shfl_down_sync(0xffffffffu, v[i], k);
        }
        if (lane == 0) {
#pragma unroll
            for (int i = 0; i < 10; i++) s_warp[wid][i] = v[i];
        }
    }
    __syncthreads();
    if (t < 10) {
        float acc = 0.f;
#pragma unroll
        for (int w = 0; w < 8; w++) acc += s_warp[w][t];
        s_stats[t] = acc;
    }
    __syncthreads();

    int n = blockIdx.x * blockDim.x + t;
    if (n >= N_NODES) return;
    const float inv_n = 1.f / (float)N_NODES;
    float xr[5];
#pragma unroll
    for (int i = 0; i < 5; i++) {
        float mu = s_stats[i] * inv_n;
        float var = s_stats[5 + i] * inv_n - mu * mu;
        float sc = rsqrtf(var + EPS_BN) * gamma[i];
        xr[i] = (h[n * 5 + i] - mu) * sc + beta[i];
    }
    float4* x0v = reinterpret_cast<float4*>(x0p + (size_t)n * 8);
    x0v[0] = make_float4(xr[0], xr[1], xr[2], xr[3]);
    x0v[1] = make_float4(xr[4], 0.f, 0.f, 0.f);
    float xp[5];
#pragma unroll
    for (int k = 0; k < 5; k++) {
        float v = pb[k];
#pragma unroll
        for (int i = 0; i < 5; i++) v += xr[i] * pw[i * 5 + k];
        xp[k] = fmaxf(v, 0.f);
    }
    __half2 h0 = __floats2half2_rn(xp[0], xp[1]);
    __half2 h1 = __floats2half2_rn(xp[2], xp[3]);
    __half2 h2 = __floats2half2_rn(xp[4], 0.f);
    uint4 pack;
    pack.x = *reinterpret_cast<uint32_t*>(&h0);
    pack.y = *reinterpret_cast<uint32_t*>(&h1);
    pack.z = *reinterpret_cast<uint32_t*>(&h2);
    pack.w = 0u;
    *reinterpret_cast<uint4*>(y8 + (size_t)n * 8) = pack;
    float4* av = reinterpret_cast<float4*>(agg8 + (size_t)n * 8);
    float4 z = make_float4(0.f, 0.f, 0.f, 0.f);
    av[0] = z;
    av[1] = z;
}

// -------- width-8 push scatter (R6 form: one edge per thread) --------
template <bool ADD_CNT>
__global__ void scatter8_kernel(const int* __restrict__ src,
                                const int* __restrict__ dst,
                                const float* __restrict__ ew,
                                const __half* __restrict__ y8,
                                float* __restrict__ agg8) {
    int stride = gridDim.x * blockDim.x;
    for (int e = blockIdx.x * blockDim.x + threadIdx.x; e < N_EDGES; e += stride) {
        int s = __ldg(&src[e]);
        int d = __ldg(&dst[e]);
        float w = __ldg(&ew[e]);
        uint4 raw = *reinterpret_cast<const uint4*>(y8 + (size_t)s * 8);
        float2 f0 = __half22float2(*reinterpret_cast<__half2*>(&raw.x));
        float2 f1 = __half22float2(*reinterpret_cast<__half2*>(&raw.y));
        float2 f2 = __half22float2(*reinterpret_cast<__half2*>(&raw.z));
        red_add_v4(agg8 + (size_t)d * 8,
                   make_float4(f0.x * w, f0.y * w, f1.x * w, f1.y * w));
        if (ADD_CNT)
            red_add_v2(agg8 + (size_t)d * 8 + 4, f2.x * w, 1.0f);
        else
            red_add_f32(agg8 + (size_t)d * 8 + 4, f2.x * w);
    }
}

// -------- width-64 push scatter: fp16 reads AND fp16 atomics --------
__global__ void scatter64_kernel(const int* __restrict__ src,
                                 const int* __restrict__ dst,
                                 const float* __restrict__ ew,
                                 const __half* __restrict__ y,
                                 __half* __restrict__ agg) {
    int lane = threadIdx.x & 31;
    int warp = (blockIdx.x * blockDim.x + threadIdx.x) >> 5;
    int nwarps = (gridDim.x * blockDim.x) >> 5;
    int half = lane >> 4;         // which edge of the pair
    int fq = (lane & 15) << 2;    // feature offset (4 halves)
    const int npairs = N_EDGES / 2;
    for (int p = warp; p < npairs; p += nwarps) {
        int e = 2 * p + half;
        int s = __ldg(&src[e]);
        int d = __ldg(&dst[e]);
        float w = __ldg(&ew[e]);
        uint2 raw = *reinterpret_cast<const uint2*>(y + (size_t)s * 64 + fq);
        float2 f0 = __half22float2(*reinterpret_cast<__half2*>(&raw.x));
        float2 f1 = __half22float2(*reinterpret_cast<__half2*>(&raw.y));
        __half2 h0 = __floats2half2_rn(f0.x * w, f0.y * w);
        __half2 h1 = __floats2half2_rn(f1.x * w, f1.y * w);
        red_add_v2_h2(agg + (size_t)d * 64 + fq,
                      *reinterpret_cast<uint32_t*>(&h0),
                      *reinterpret_cast<uint32_t*>(&h1));
    }
}

// ------- conv1 finalize: 64 nodes/block, 256 threads, K=10 GEMM -------
__global__ __launch_bounds__(256) void fin1_kernel(const float* __restrict__ x0p,
                                                   const float* __restrict__ agg8,
                                                   const float* __restrict__ lw,
                                                   const float* __restrict__ lb,
                                                   const float* __restrict__ rw,
                                                   float* __restrict__ x1,
                                                   float* __restrict__ cinv_out) {
    __shared__ float s_w[10 * 64];
    __shared__ float s_x[10][72];
    __shared__ float s_lb[64];
    __shared__ float s_ci[64];
    const int t = threadIdx.x;
    const int n0 = blockIdx.x * 64;

    for (int idx = t; idx < 640; idx += 256)
        s_w[idx] = (idx < 320) ? lw[idx] : rw[idx - 320];
    if (t < 64) s_lb[t] = lb[t];
    if (t < 64) {
        int nn = min(n0 + t, N_NODES - 1);
        float c = agg8[(size_t)nn * 8 + 5];
        float ci = 1.f / fmaxf(c, 1.f);
        s_ci[t] = ci;
        if (n0 + t < N_NODES) cinv_out[n0 + t] = ci;
    }
    __syncthreads();
    for (int idx = t; idx < 640; idx += 256) {
        int i = idx >> 6, nd = idx & 63;
        int nn = min(n0 + nd, N_NODES - 1);
        s_x[i][nd] = (i < 5) ? agg8[(size_t)nn * 8 + i] * s_ci[nd]
                             : x0p[(size_t)nn * 8 + (i - 5)];
    }
    __syncthreads();

    const int oq = t & 15, nq = t >> 4;
    float acc[4][4];
#pragma unroll
    for (int a = 0; a < 4; a++)
#pragma unroll
        for (int b = 0; b < 4; b++) acc[a][b] = 0.f;
#pragma unroll
    for (int i = 0; i < 10; i++) {
        float4 xv = *reinterpret_cast<const float4*>(&s_x[i][nq << 2]);
        float4 wv = *reinterpret_cast<const float4*>(&s_w[(i << 6) + (oq << 2)]);
        acc[0][0] += xv.x * wv.x; acc[0][1] += xv.x * wv.y; acc[0][2] += xv.x * wv.z; acc[0][3] += xv.x * wv.w;
        acc[1][0] += xv.y * wv.x; acc[1][1] += xv.y * wv.y; acc[1][2] += xv.y * wv.z; acc[1][3] += xv.y * wv.w;
        acc[2][0] += xv.z * wv.x; acc[2][1] += xv.z * wv.y; acc[2][2] += xv.z * wv.z; acc[2][3] += xv.z * wv.w;
        acc[3][0] += xv.w * wv.x; acc[3][1] += xv.w * wv.y; acc[3][2] += xv.w * wv.z; acc[3][3] += xv.w * wv.w;
    }

    float lb0 = s_lb[(oq << 2) + 0], lb1 = s_lb[(oq << 2) + 1];
    float lb2 = s_lb[(oq << 2) + 2], lb3 = s_lb[(oq << 2) + 3];
#pragma unroll
    for (int dn = 0; dn < 4; dn++) {
        int n = n0 + (nq << 2) + dn;
        float v0 = acc[dn][0] + lb0;
        float v1 = acc[dn][1] + lb1;
        float v2 = acc[dn][2] + lb2;
        float v3 = acc[dn][3] + lb3;
        float ss = v0 * v0 + v1 * v1 + v2 * v2 + v3 * v3;
        ss += __shfl_down_sync(0xffffffffu, ss, 8, 16);
        ss += __shfl_down_sync(0xffffffffu, ss, 4, 16);
        ss += __shfl_down_sync(0xffffffffu, ss, 2, 16);
        ss += __shfl_down_sync(0xffffffffu, ss, 1, 16);
        ss = __shfl_sync(0xffffffffu, ss, 0, 16);
        float sc = 1.f / fmaxf(sqrtf(ss), EPS_NORM);
        if (n < N_NODES) {
            float4 o4 = make_float4(fmaxf(v0 * sc, 0.f), fmaxf(v1 * sc, 0.f),
                                    fmaxf(v2 * sc, 0.f), fmaxf(v3 * sc, 0.f));
            *reinterpret_cast<float4*>(&x1[(size_t)n * 64 + (oq << 2)]) = o4;
        }
    }
}

// -------- y(half) = relu(x@pw + pb) @ lw  (64 -> 64 -> OUT2) --------
// 64 nodes/block, 256 threads; s_xp aliases s_x (reads complete before overwrite)
template <int OUT2>
__global__ __launch_bounds__(256) void proj_lw_kernel(const float* __restrict__ x,
                                                      const float* __restrict__ pw,
                                                      const float* __restrict__ pb,
                                                      const float* __restrict__ lw,
                                                      __half* __restrict__ y,
                                                      void* __restrict__ zero_base,
                                                      int zero_f4_per_blk,
                                                      int zero_f4_total) {
    constexpr int OUTP = (OUT2 == 64) ? 64 : 8;
    constexpr int YS = (OUT2 == 64) ? 64 : 8;
    constexpr int XS = 68;
    __shared__ float s_w[64 * 64];
    __shared__ float s_x[64 * XS];   // holds x, then reused as xp
    __shared__ float s_pb[64];
    const int t = threadIdx.x;
    const int n0 = blockIdx.x * 64;

    if (zero_base) {
        float4 z = make_float4(0.f, 0.f, 0.f, 0.f);
        float4* zb = reinterpret_cast<float4*>(zero_base);
        int base = blockIdx.x * zero_f4_per_blk;
        for (int i = t; i < zero_f4_per_blk; i += 256) {
            int gi = base + i;
            if (gi < zero_f4_total) zb[gi] = z;
        }
    }

    for (int i4 = t; i4 < 1024; i4 += 256)
        reinterpret_cast<float4*>(s_w)[i4] = reinterpret_cast<const float4*>(pw)[i4];
    if (t < 64) s_pb[t] = pb[t];
    for (int idx = t; idx < 64 * 64; idx += 256) {
        int n = idx >> 6, i = idx & 63;
        int nn = min(n0 + n, N_NODES - 1);
        s_x[i * XS + n] = x[(size_t)nn * 64 + i];
    }
    __syncthreads();

    const int oq = t & 15, nq = t >> 4;
    float acc[4][4];
#pragma unroll
    for (int a = 0; a < 4; a++)
#pragma unroll
        for (int b = 0; b < 4; b++) acc[a][b] = 0.f;

#pragma unroll 8
    for (int i = 0; i < 64; i++) {
        float4 xv = *reinterpret_cast<const float4*>(&s_x[i * XS + (nq << 2)]);
        float4 wv = *reinterpret_cast<const float4*>(&s_w[(i << 6) + (oq << 2)]);
        acc[0][0] += xv.x * wv.x; acc[0][1] += xv.x * wv.y; acc[0][2] += xv.x * wv.z; acc[0][3] += xv.x * wv.w;
        acc[1][0] += xv.y * wv.x; acc[1][1] += xv.y * wv.y; acc[1][2] += xv.y * wv.z; acc[1][3] += xv.y * wv.w;
        acc[2][0] += xv.z * wv.x; acc[2][1] += xv.z * wv.y; acc[2][2] += xv.z * wv.z; acc[2][3] += xv.z * wv.w;
        acc[3][0] += xv.w * wv.x; acc[3][1] += xv.w * wv.y; acc[3][2] += xv.w * wv.z; acc[3][3] += xv.w * wv.w;
    }
    __syncthreads();   // all reads of s_x / s_w complete

    // overwrite s_x with xp; reload s_w with lw
#pragma unroll
    for (int dk = 0; dk < 4; dk++) {
        float b = s_pb[(oq << 2) + dk];
#pragma unroll
        for (int dn = 0; dn < 4; dn++) {
            s_x[((oq << 2) + dk) * XS + (nq << 2) + dn] = fmaxf(acc[dn][dk] + b, 0.f);
        }
    }
    if (OUT2 == 64) {
        for (int i4 = t; i4 < 1024; i4 += 256)
            reinterpret_cast<float4*>(s_w)[i4] = reinterpret_cast<const float4*>(lw)[i4];
        __syncthreads();
    } else {
        for (int idx = t; idx < 64 * 8; idx += 256) s_w[idx] = 0.f;
        __syncthreads();
        for (int idx = t; idx < 64 * 5; idx += 256) s_w[(idx / 5) * 8 + (idx % 5)] = lw[idx];
        __syncthreads();
    }

    constexpr int OQ2 = OUTP / 4;
    if (oq < OQ2) {
        float a2[4][4];
#pragma unroll
        for (int a = 0; a < 4; a++)
#pragma unroll
            for (int b = 0; b < 4; b++) a2[a][b] = 0.f;
#pragma unroll 8
        for (int i = 0; i < 64; i++) {
            float4 xv = *reinterpret_cast<const float4*>(&s_x[i * XS + (nq << 2)]);
            float4 wv = *reinterpret_cast<const float4*>(&s_w[i * OUTP + (oq << 2)]);
            a2[0][0] += xv.x * wv.x; a2[0][1] += xv.x * wv.y; a2[0][2] += xv.x * wv.z; a2[0][3] += xv.x * wv.w;
            a2[1][0] += xv.y * wv.x; a2[1][1] += xv.y * wv.y; a2[1][2] += xv.y * wv.z; a2[1][3] += xv.y * wv.w;
            a2[2][0] += xv.z * wv.x; a2[2][1] += xv.z * wv.y; a2[2][2] += xv.z * wv.z; a2[2][3] += xv.z * wv.w;
            a2[3][0] += xv.w * wv.x; a2[3][1] += xv.w * wv.y; a2[3][2] += xv.w * wv.z; a2[3][3] += xv.w * wv.w;
        }
#pragma unroll
        for (int dn = 0; dn < 4; dn++) {
            int n = n0 + (nq << 2) + dn;
            if (n < N_NODES) {
                __half2 h0 = __floats2half2_rn(a2[dn][0], a2[dn][1]);
                __half2 h1 = __floats2half2_rn(a2[dn][2], a2[dn][3]);
                uint2 pack;
                pack.x = *reinterpret_cast<uint32_t*>(&h0);
                pack.y = *reinterpret_cast<uint32_t*>(&h1);
                *reinterpret_cast<uint2*>(y + (size_t)n * YS + (oq << 2)) = pack;
            }
        }
    }
}

// ------- conv2 finalize: 64 nodes/block, 256 threads ; zero agg8 -------
__global__ __launch_bounds__(256) void fin64_kernel(const float* __restrict__ x,
                                                    const __half* __restrict__ agg,
                                                    const float* __restrict__ cinv,
                                                    const float* __restrict__ rw,
                                                    const float* __restrict__ lb,
                                                    float* __restrict__ out,
                                                    float* __restrict__ agg8z) {
    constexpr int XS = 68;
    __shared__ float s_w[64 * 64];
    __shared__ float s_x[64 * XS];
    __shared__ float s_lb[64];
    const int t = threadIdx.x;
    const int n0 = blockIdx.x * 64;

    if (t < 128) {
        int gi = blockIdx.x * 128 + t;
        if (gi < N_NODES * 2) {
            float4 z = make_float4(0.f, 0.f, 0.f, 0.f);
            reinterpret_cast<float4*>(agg8z)[gi] = z;
        }
    }

    for (int i4 = t; i4 < 1024; i4 += 256)
        reinterpret_cast<float4*>(s_w)[i4] = reinterpret_cast<const float4*>(rw)[i4];
    if (t < 64) s_lb[t] = lb[t];
    for (int idx = t; idx < 64 * 64; idx += 256) {
        int n = idx >> 6, i = idx & 63;
        int nn = min(n0 + n, N_NODES - 1);
        s_x[i * XS + n] = x[(size_t)nn * 64 + i];
    }
    __syncthreads();

    const int oq = t & 15, nq = t >> 4;
    float acc[4][4];
#pragma unroll
    for (int a = 0; a < 4; a++)
#pragma unroll
        for (int b = 0; b < 4; b++) acc[a][b] = 0.f;
#pragma unroll 8
    for (int i = 0; i < 64; i++) {
        float4 xv = *reinterpret_cast<const float4*>(&s_x[i * XS + (nq << 2)]);
        float4 wv = *reinterpret_cast<const float4*>(&s_w[(i << 6) + (oq << 2)]);
        acc[0][0] += xv.x * wv.x; acc[0][1] += xv.x * wv.y; acc[0][2] += xv.x * wv.z; acc[0][3] += xv.x * wv.w;
        acc[1][0] += xv.y * wv.x; acc[1][1] += xv.y * wv.y; acc[1][2] += xv.y * wv.z; acc[1][3] += xv.y * wv.w;
        acc[2][0] += xv.z * wv.x; acc[2][1] += xv.z * wv.y; acc[2][2] += xv.z * wv.z; acc[2][3] += xv.z * wv.w;
        acc[3][0] += xv.w * wv.x; acc[3][1] += xv.w * wv.y; acc[3][2] += xv.w * wv.z; acc[3][3] += xv.w * wv.w;
    }

    float lb0 = s_lb[(oq << 2) + 0], lb1 = s_lb[(oq << 2) + 1];
    float lb2 = s_lb[(oq << 2) + 2], lb3 = s_lb[(oq << 2) + 3];
#pragma unroll
    for (int dn = 0; dn < 4; dn++) {
        int n = n0 + (nq << 2) + dn;
        int nn = min(n, N_NODES - 1);
        float ci = cinv[nn];
        uint2 raw = *reinterpret_cast<const uint2*>(agg + (size_t)nn * 64 + (oq << 2));
        float2 g0 = __half22float2(*reinterpret_cast<__half2*>(&raw.x));
        float2 g1 = __half22float2(*reinterpret_cast<__half2*>(&raw.y));
        float v0 = acc[dn][0] + lb0 + g0.x * ci;
        float v1 = acc[dn][1] + lb1 + g0.y * ci;
        float v2 = acc[dn][2] + lb2 + g1.x * ci;
        float v3 = acc[dn][3] + lb3 + g1.y * ci;
        float ss = v0 * v0 + v1 * v1 + v2 * v2 + v3 * v3;
        ss += __shfl_down_sync(0xffffffffu, ss, 8, 16);
        ss += __shfl_down_sync(0xffffffffu, ss, 4, 16);
        ss += __shfl_down_sync(0xffffffffu, ss, 2, 16);
        ss += __shfl_down_sync(0xffffffffu, ss, 1, 16);
        ss = __shfl_sync(0xffffffffu, ss, 0, 16);
        float sc = 1.f / fmaxf(sqrtf(ss), EPS_NORM);
        if (n < N_NODES) {
            float4 o4 = make_float4(fmaxf(v0 * sc, 0.f), fmaxf(v1 * sc, 0.f),
                                    fmaxf(v2 * sc, 0.f), fmaxf(v3 * sc, 0.f));
            *reinterpret_cast<float4*>(&out[(size_t)n * 64 + (oq << 2)]) = o4;
        }
    }
}

// ------- conv3 finalize: out5 = agg*cinv + lb + x2@rw ; norm (no relu) -------
__global__ __launch_bounds__(128) void fin3_kernel(const float* __restrict__ x2,
                                                   const float* __restrict__ agg8,
                                                   const float* __restrict__ cinv,
                                                   const float* __restrict__ rw,
                                                   const float* __restrict__ lb,
                                                   float* __restrict__ out) {
    __shared__ float s_rw[64 * 8];
    __shared__ float s_lb[8];
    int t = threadIdx.x;
    for (int idx = t; idx < 320; idx += 128) s_rw[(idx / 5) * 8 + (idx % 5)] = rw[idx];
    if (t < 5) s_lb[t] = lb[t];
    __syncthreads();
    int n = blockIdx.x * 128 + t;
    if (n >= N_NODES) return;

    float ci = cinv[n];
    const float4* av = reinterpret_cast<const float4*>(agg8 + (size_t)n * 8);
    float4 a0 = av[0], a1 = av[1];
    float4 vf = make_float4(s_lb[0] + a0.x * ci, s_lb[1] + a0.y * ci,
                            s_lb[2] + a0.z * ci, s_lb[3] + a0.w * ci);
    float v4 = s_lb[4] + a1.x * ci;

    const float4* xr = reinterpret_cast<const float4*>(x2 + (size_t)n * 64);
#pragma unroll
    for (int iq = 0; iq < 16; iq++) {
        float4 xv = xr[iq];
        float xs[4] = {xv.x, xv.y, xv.z, xv.w};
#pragma unroll
        for (int c = 0; c < 4; c++) {
            int i = iq * 4 + c;
            float4 w = *reinterpret_cast<const float4*>(&s_rw[i * 8]);
            float w4 = s_rw[i * 8 + 4];
            vf.x += xs[c] * w.x;
            vf.y += xs[c] * w.y;
            vf.z += xs[c] * w.z;
            vf.w += xs[c] * w.w;
            v4 += xs[c] * w4;
        }
    }
    float ss = vf.x * vf.x + vf.y * vf.y + vf.z * vf.z + vf.w * vf.w + v4 * v4;
    float sc = 1.f / fmaxf(sqrtf(ss), EPS_NORM);
    float* o = out + (size_t)n * 5;
    o[0] = vf.x * sc;
    o[1] = vf.y * sc;
    o[2] = vf.z * sc;
    o[3] = vf.w * sc;
    o[4] = v4 * sc;
}

// ---------------- host launcher ----------------
extern "C" void kernel_launch(void* const* d_in, const int* in_sizes, int n_in,
                              void* d_out, int out_size) {
    const float* h = (const float*)d_in[0];
    const int* ei = (const int*)d_in[1];
    const float* ew = (const float*)d_in[2];
    const float* gamma = (const float*)d_in[3];
    const float* beta = (const float*)d_in[4];
    const float* c1_pw = (const float*)d_in[5];
    const float* c1_pb = (const float*)d_in[6];
    const float* c1_lw = (const float*)d_in[7];
    const float* c1_lb = (const float*)d_in[8];
    const float* c1_rw = (const float*)d_in[9];
    const float* c2_pw = (const float*)d_in[10];
    const float* c2_pb = (const float*)d_in[11];
    const float* c2_lw = (const float*)d_in[12];
    const float* c2_lb = (const float*)d_in[13];
    const float* c2_rw = (const float*)d_in[14];
    const float* c3_pw = (const float*)d_in[15];
    const float* c3_pb = (const float*)d_in[16];
    const float* c3_lw = (const float*)d_in[17];
    const float* c3_lb = (const float*)d_in[18];
    const float* c3_rw = (const float*)d_in[19];
    float* out = (float*)d_out;

    const int* src = ei;
    const int* dst = ei + N_EDGES;

    float *x0, *x1, *x2, *agg8, *cinv, *part;
    __half *yh, *aggh;
    cudaGetSymbolAddress((void**)&x0, g_x0);
    cudaGetSymbolAddress((void**)&x1, g_x1);
    cudaGetSymbolAddress((void**)&x2, g_x2);
    cudaGetSymbolAddress((void**)&yh, g_yh);
    cudaGetSymbolAddress((void**)&aggh, g_aggh);
    cudaGetSymbolAddress((void**)&agg8, g_agg8);
    cudaGetSymbolAddress((void**)&cinv, g_cinv);
    cudaGetSymbolAddress((void**)&part, g_part);

    const int NB64 = (N_NODES + 63) / 64;   // 1563

    // 1: BN partial stats
    bn_stats_kernel<<<148, 256>>>(h, part);
    // 2: BN apply + conv1 5x5 projection (fp16 y8); zeroes agg8
    bn_conv1_kernel<<<(N_NODES + 255) / 256, 256>>>(h, part, gamma, beta, c1_pw, c1_pb,
                                                    x0, yh, agg8);
    // 3: conv1 push-scatter (width 5 + cnt)
    scatter8_kernel<true><<<6250, 256>>>(src, dst, ew, yh, agg8);
    // 4: conv1 finalize (64 nodes/block) — CAPTURED BY NCU
    fin1_kernel<<<NB64, 256>>>(x0, agg8, c1_lw, c1_lb, c1_rw, x1, cinv);
    // 5: conv2 projection (zeroes aggh: 64 nodes*64 halves = 512 f4/block)
    proj_lw_kernel<64><<<NB64, 256>>>(x1, c2_pw, c2_pb, c2_lw, yh, aggh, 512,
                                      N_NODES * 64 / 8);
    // 6: conv2 push-scatter (fp16 atomics)
    scatter64_kernel<<<4096, 256>>>(src, dst, ew, yh, aggh);
    // 7: conv2 finalize (zeroes agg8 for conv3)
    fin64_kernel<<<NB64, 256>>>(x1, aggh, cinv, c2_rw, c2_lb, x2, agg8);
    // 8: conv3 projection
    proj_lw_kernel<5><<<NB64, 256>>>(x2, c3_pw, c3_pb, c3_lw, yh, nullptr, 0, 0);
    // 9: conv3 push-scatter (width 5)
    scatter8_kernel<false><<<6250, 256>>>(src, dst, ew, yh, agg8);
    // 10: conv3 finalize
    fin3_kernel<<<(N_NODES + 127) / 128, 128>>>(x2, agg8, cinv, c3_rw, c3_lb, out);
}

// round 10
// speedup vs baseline: 1.6234x; 1.0006x over previous
#include <cuda_runtime.h>
#include <cuda_fp16.h>
#include <cstdint>
#include <math.h>

#define N_NODES 100000
#define N_EDGES 3200000
#define EPS_BN 1e-5f
#define EPS_NORM 1e-12f

// ---------------- device scratch (no allocation allowed) ----------------
__device__ __align__(16) float g_x0[N_NODES * 8];     // BN output (padded stride 8)
__device__ __align__(16) float g_x1[N_NODES * 64];    // conv1 output
__device__ __align__(16) float g_x2[N_NODES * 64];    // conv2 output
__device__ __align__(16) __half g_yh[N_NODES * 64];   // fp16 projected features (stride 64 or 8)
__device__ __align__(16) __half g_aggh[N_NODES * 64]; // conv2 accumulator (fp16 atomics)
__device__ __align__(32) float g_agg8[N_NODES * 8];   // conv1/conv3 accumulator (5 feats + cnt)
__device__ float g_cinv[N_NODES];                     // 1/max(cnt,1)
__device__ __align__(16) float g_part[148 * 16];      // BN per-block partials

// ---------------- vector reductions ----------------
__device__ __forceinline__ void red_add_v4(float* p, float4 v) {
    asm volatile("red.global.add.v4.f32 [%0], {%1,%2,%3,%4};"
                 :: "l"(p), "f"(v.x), "f"(v.y), "f"(v.z), "f"(v.w) : "memory");
}
__device__ __forceinline__ void red_add_v2(float* p, float a, float b) {
    asm volatile("red.global.add.v2.f32 [%0], {%1,%2};"
                 :: "l"(p), "f"(a), "f"(b) : "memory");
}
__device__ __forceinline__ void red_add_f32(float* p, float a) {
    asm volatile("red.global.add.f32 [%0], %1;"
                 :: "l"(p), "f"(a) : "memory");
}
__device__ __forceinline__ void red_add_v2_h2(__half* p, uint32_t a, uint32_t b) {
    asm volatile("red.global.add.noftz.v2.f16x2 [%0], {%1,%2};"
                 :: "l"(p), "r"(a), "r"(b) : "memory");
}

// ------- BatchNorm statistics: per-block partials (no pre-zeroing) -------
__global__ __launch_bounds__(256) void bn_stats_kernel(const float* __restrict__ h,
                                                       float* __restrict__ part) {
    float s[5] = {0, 0, 0, 0, 0}, q[5] = {0, 0, 0, 0, 0};
    int stride = gridDim.x * blockDim.x;
    for (int n = blockIdx.x * blockDim.x + threadIdx.x; n < N_NODES; n += stride) {
#pragma unroll
        for (int i = 0; i < 5; i++) {
            float v = h[n * 5 + i];
            s[i] += v;
            q[i] += v * v;
        }
    }
#pragma unroll
    for (int k = 16; k > 0; k >>= 1) {
#pragma unroll
        for (int i = 0; i < 5; i++) {
            s[i] += __shfl_down_sync(0xffffffffu, s[i], k);
            q[i] += __shfl_down_sync(0xffffffffu, q[i], k);
        }
    }
    __shared__ float sh[10];
    if (threadIdx.x < 10) sh[threadIdx.x] = 0.f;
    __syncthreads();
    if ((threadIdx.x & 31) == 0) {
#pragma unroll
        for (int i = 0; i < 5; i++) {
            atomicAdd(&sh[i], s[i]);
            atomicAdd(&sh[5 + i], q[i]);
        }
    }
    __syncthreads();
    if (threadIdx.x < 10) part[blockIdx.x * 16 + threadIdx.x] = sh[threadIdx.x];
}

// ------- BN apply + conv1 projection (5x5) -> fp16 y8 ; zero agg8 -------
__global__ __launch_bounds__(256) void bn_conv1_kernel(const float* __restrict__ h,
                                                       const float* __restrict__ part,
                                                       const float* __restrict__ gamma,
                                                       const float* __restrict__ beta,
                                                       const float* __restrict__ pw,
                                                       const float* __restrict__ pb,
                                                       float* __restrict__ x0p,
                                                       __half* __restrict__ y8,
                                                       float* __restrict__ agg8) {
    __shared__ float s_warp[8][10];
    __shared__ float s_stats[10];
    int t = threadIdx.x;
    int lane = t & 31, wid = t >> 5;
    {
        float v[10];
#pragma unroll
        for (int i = 0; i < 10; i++) v[i] = 0.f;
        if (t < 148) {
#pragma unroll
            for (int i = 0; i < 10; i++) v[i] = part[t * 16 + i];
        }
#pragma unroll
        for (int k = 16; k > 0; k >>= 1) {
#pragma unroll
            for (int i = 0; i < 10; i++) v[i] += __shfl_down_sync(0xffffffffu, v[i], k);
        }
        if (lane == 0) {
#pragma unroll
            for (int i = 0; i < 10; i++) s_warp[wid][i] = v[i];
        }
    }
    __syncthreads();
    if (t < 10) {
        float acc = 0.f;
#pragma unroll
        for (int w = 0; w < 8; w++) acc += s_warp[w][t];
        s_stats[t] = acc;
    }
    __syncthreads();

    int n = blockIdx.x * blockDim.x + t;
    if (n >= N_NODES) return;
    const float inv_n = 1.f / (float)N_NODES;
    float xr[5];
#pragma unroll
    for (int i = 0; i < 5; i++) {
        float mu = s_stats[i] * inv_n;
        float var = s_stats[5 + i] * inv_n - mu * mu;
        float sc = rsqrtf(var + EPS_BN) * gamma[i];
        xr[i] = (h[n * 5 + i] - mu) * sc + beta[i];
    }
    float4* x0v = reinterpret_cast<float4*>(x0p + (size_t)n * 8);
    x0v[0] = make_float4(xr[0], xr[1], xr[2], xr[3]);
    x0v[1] = make_float4(xr[4], 0.f, 0.f, 0.f);
    float xp[5];
#pragma unroll
    for (int k = 0; k < 5; k++) {
        float v = pb[k];
#pragma unroll
        for (int i = 0; i < 5; i++) v += xr[i] * pw[i * 5 + k];
        xp[k] = fmaxf(v, 0.f);
    }
    __half2 h0 = __floats2half2_rn(xp[0], xp[1]);
    __half2 h1 = __floats2half2_rn(xp[2], xp[3]);
    __half2 h2 = __floats2half2_rn(xp[4], 0.f);
    uint4 pack;
    pack.x = *reinterpret_cast<uint32_t*>(&h0);
    pack.y = *reinterpret_cast<uint32_t*>(&h1);
    pack.z = *reinterpret_cast<uint32_t*>(&h2);
    pack.w = 0u;
    *reinterpret_cast<uint4*>(y8 + (size_t)n * 8) = pack;
    float4* av = reinterpret_cast<float4*>(agg8 + (size_t)n * 8);
    float4 z = make_float4(0.f, 0.f, 0.f, 0.f);
    av[0] = z;
    av[1] = z;
}

// -------- width-8 push scatter (one edge per thread) --------
template <bool ADD_CNT>
__global__ void scatter8_kernel(const int* __restrict__ src,
                                const int* __restrict__ dst,
                                const float* __restrict__ ew,
                                const __half* __restrict__ y8,
                                float* __restrict__ agg8) {
    int stride = gridDim.x * blockDim.x;
    for (int e = blockIdx.x * blockDim.x + threadIdx.x; e < N_EDGES; e += stride) {
        int s = __ldg(&src[e]);
        int d = __ldg(&dst[e]);
        float w = __ldg(&ew[e]);
        uint4 raw = *reinterpret_cast<const uint4*>(y8 + (size_t)s * 8);
        float2 f0 = __half22float2(*reinterpret_cast<__half2*>(&raw.x));
        float2 f1 = __half22float2(*reinterpret_cast<__half2*>(&raw.y));
        float2 f2 = __half22float2(*reinterpret_cast<__half2*>(&raw.z));
        red_add_v4(agg8 + (size_t)d * 8,
                   make_float4(f0.x * w, f0.y * w, f1.x * w, f1.y * w));
        if (ADD_CNT)
            red_add_v2(agg8 + (size_t)d * 8 + 4, f2.x * w, 1.0f);
        else
            red_add_f32(agg8 + (size_t)d * 8 + 4, f2.x * w);
    }
}

// -------- width-64 push scatter: fp16 reads AND fp16 atomics --------
__global__ void scatter64_kernel(const int* __restrict__ src,
                                 const int* __restrict__ dst,
                                 const float* __restrict__ ew,
                                 const __half* __restrict__ y,
                                 __half* __restrict__ agg) {
    int lane = threadIdx.x & 31;
    int warp = (blockIdx.x * blockDim.x + threadIdx.x) >> 5;
    int nwarps = (gridDim.x * blockDim.x) >> 5;
    int half = lane >> 4;
    int fq = (lane & 15) << 2;
    const int npairs = N_EDGES / 2;
    for (int p = warp; p < npairs; p += nwarps) {
        int e = 2 * p + half;
        int s = __ldg(&src[e]);
        int d = __ldg(&dst[e]);
        float w = __ldg(&ew[e]);
        uint2 raw = *reinterpret_cast<const uint2*>(y + (size_t)s * 64 + fq);
        float2 f0 = __half22float2(*reinterpret_cast<__half2*>(&raw.x));
        float2 f1 = __half22float2(*reinterpret_cast<__half2*>(&raw.y));
        __half2 h0 = __floats2half2_rn(f0.x * w, f0.y * w);
        __half2 h1 = __floats2half2_rn(f1.x * w, f1.y * w);
        red_add_v2_h2(agg + (size_t)d * 64 + fq,
                      *reinterpret_cast<uint32_t*>(&h0),
                      *reinterpret_cast<uint32_t*>(&h1));
    }
}

// ==================== fp1: conv1 finalize + conv2 projection ====================
// GEMM0: out64 = [mean5;x0] @ [lw1;rw1] + lb1 ; norm ; relu -> x1 (global + smem^T)
// GEMM1: xp = relu(x1 @ pw2 + pb2)   GEMM2: y(half) = xp @ lw2 ; zero aggh
__global__ __launch_bounds__(256) void fp1_kernel(const float* __restrict__ x0p,
                                                  const float* __restrict__ agg8,
                                                  const float* __restrict__ lw1,
                                                  const float* __restrict__ lb1,
                                                  const float* __restrict__ rw1,
                                                  const float* __restrict__ pw2,
                                                  const float* __restrict__ pb2,
                                                  const float* __restrict__ lw2,
                                                  float* __restrict__ x1,
                                                  float* __restrict__ cinv_out,
                                                  __half* __restrict__ y,
                                                  __half* __restrict__ aggh_zero) {
    constexpr int XS = 68;
    __shared__ float s_w[64 * 64];
    __shared__ float s_x[64 * XS];
    __shared__ float s_b[64];
    __shared__ float s_ci[64];
    const int t = threadIdx.x;
    const int n0 = blockIdx.x * 64;
    const int oq = t & 15, nq = t >> 4;

    // zero aggh slice: 64 nodes * 64 halves = 512 float4
    {
        float4 z = make_float4(0.f, 0.f, 0.f, 0.f);
        float4* zb = reinterpret_cast<float4*>(aggh_zero);
        int base = blockIdx.x * 512;
        for (int i = t; i < 512; i += 256) {
            int gi = base + i;
            if (gi < N_NODES * 8) zb[gi] = z;
        }
    }

    // ---- stage GEMM0 operands: w10 in s_w front, x10 in s_x front ----
    for (int idx = t; idx < 640; idx += 256)
        s_w[idx] = (idx < 320) ? lw1[idx] : rw1[idx - 320];
    if (t < 64) s_b[t] = lb1[t];
    if (t < 64) {
        int nn = min(n0 + t, N_NODES - 1);
        float c = agg8[(size_t)nn * 8 + 5];
        float ci = 1.f / fmaxf(c, 1.f);
        s_ci[t] = ci;
        if (n0 + t < N_NODES) cinv_out[n0 + t] = ci;
    }
    __syncthreads();
    for (int idx = t; idx < 640; idx += 256) {
        int i = idx >> 6, nd = idx & 63;
        int nn = min(n0 + nd, N_NODES - 1);
        s_x[i * 72 + nd] = (i < 5) ? agg8[(size_t)nn * 8 + i] * s_ci[nd]
                                   : x0p[(size_t)nn * 8 + (i - 5)];
    }
    __syncthreads();

    // ---- GEMM0: K=10 ----
    float acc[4][4];
#pragma unroll
    for (int a = 0; a < 4; a++)
#pragma unroll
        for (int b = 0; b < 4; b++) acc[a][b] = 0.f;
#pragma unroll
    for (int i = 0; i < 10; i++) {
        float4 xv = *reinterpret_cast<const float4*>(&s_x[i * 72 + (nq << 2)]);
        float4 wv = *reinterpret_cast<const float4*>(&s_w[(i << 6) + (oq << 2)]);
        acc[0][0] += xv.x * wv.x; acc[0][1] += xv.x * wv.y; acc[0][2] += xv.x * wv.z; acc[0][3] += xv.x * wv.w;
        acc[1][0] += xv.y * wv.x; acc[1][1] += xv.y * wv.y; acc[1][2] += xv.y * wv.z; acc[1][3] += xv.y * wv.w;
        acc[2][0] += xv.z * wv.x; acc[2][1] += xv.z * wv.y; acc[2][2] += xv.z * wv.z; acc[2][3] += xv.z * wv.w;
        acc[3][0] += xv.w * wv.x; acc[3][1] += xv.w * wv.y; acc[3][2] += xv.w * wv.z; acc[3][3] += xv.w * wv.w;
    }
    // lb + norm + relu (per node dn)
    float lb0 = s_b[(oq << 2) + 0], lb1v = s_b[(oq << 2) + 1];
    float lb2 = s_b[(oq << 2) + 2], lb3 = s_b[(oq << 2) + 3];
#pragma unroll
    for (int dn = 0; dn < 4; dn++) {
        float v0 = acc[dn][0] + lb0;
        float v1 = acc[dn][1] + lb1v;
        float v2 = acc[dn][2] + lb2;
        float v3 = acc[dn][3] + lb3;
        float ss = v0 * v0 + v1 * v1 + v2 * v2 + v3 * v3;
        ss += __shfl_down_sync(0xffffffffu, ss, 8, 16);
        ss += __shfl_down_sync(0xffffffffu, ss, 4, 16);
        ss += __shfl_down_sync(0xffffffffu, ss, 2, 16);
        ss += __shfl_down_sync(0xffffffffu, ss, 1, 16);
        ss = __shfl_sync(0xffffffffu, ss, 0, 16);
        float sc = 1.f / fmaxf(sqrtf(ss), EPS_NORM);
        acc[dn][0] = fmaxf(v0 * sc, 0.f);
        acc[dn][1] = fmaxf(v1 * sc, 0.f);
        acc[dn][2] = fmaxf(v2 * sc, 0.f);
        acc[dn][3] = fmaxf(v3 * sc, 0.f);
    }
    __syncthreads();   // all GEMM0 reads done

    // write x1 global + transposed into s_x
#pragma unroll
    for (int dn = 0; dn < 4; dn++) {
        int n = n0 + (nq << 2) + dn;
        if (n < N_NODES) {
            *reinterpret_cast<float4*>(&x1[(size_t)n * 64 + (oq << 2)]) =
                make_float4(acc[dn][0], acc[dn][1], acc[dn][2], acc[dn][3]);
        }
#pragma unroll
        for (int dk = 0; dk < 4; dk++)
            s_x[((oq << 2) + dk) * XS + (nq << 2) + dn] = acc[dn][dk];
    }
    // reload weights: pw2
    for (int i4 = t; i4 < 1024; i4 += 256)
        reinterpret_cast<float4*>(s_w)[i4] = reinterpret_cast<const float4*>(pw2)[i4];
    if (t < 64) s_b[t] = pb2[t];
    __syncthreads();

    // ---- GEMM1: K=64 ----
#pragma unroll
    for (int a = 0; a < 4; a++)
#pragma unroll
        for (int b = 0; b < 4; b++) acc[a][b] = 0.f;
#pragma unroll 8
    for (int i = 0; i < 64; i++) {
        float4 xv = *reinterpret_cast<const float4*>(&s_x[i * XS + (nq << 2)]);
        float4 wv = *reinterpret_cast<const float4*>(&s_w[(i << 6) + (oq << 2)]);
        acc[0][0] += xv.x * wv.x; acc[0][1] += xv.x * wv.y; acc[0][2] += xv.x * wv.z; acc[0][3] += xv.x * wv.w;
        acc[1][0] += xv.y * wv.x; acc[1][1] += xv.y * wv.y; acc[1][2] += xv.y * wv.z; acc[1][3] += xv.y * wv.w;
        acc[2][0] += xv.z * wv.x; acc[2][1] += xv.z * wv.y; acc[2][2] += xv.z * wv.z; acc[2][3] += xv.z * wv.w;
        acc[3][0] += xv.w * wv.x; acc[3][1] += xv.w * wv.y; acc[3][2] += xv.w * wv.z; acc[3][3] += xv.w * wv.w;
    }
    __syncthreads();
#pragma unroll
    for (int dk = 0; dk < 4; dk++) {
        float b = s_b[(oq << 2) + dk];
#pragma unroll
        for (int dn = 0; dn < 4; dn++)
            s_x[((oq << 2) + dk) * XS + (nq << 2) + dn] = fmaxf(acc[dn][dk] + b, 0.f);
    }
    for (int i4 = t; i4 < 1024; i4 += 256)
        reinterpret_cast<float4*>(s_w)[i4] = reinterpret_cast<const float4*>(lw2)[i4];
    __syncthreads();

    // ---- GEMM2: K=64 -> y fp16 ----
#pragma unroll
    for (int a = 0; a < 4; a++)
#pragma unroll
        for (int b = 0; b < 4; b++) acc[a][b] = 0.f;
#pragma unroll 8
    for (int i = 0; i < 64; i++) {
        float4 xv = *reinterpret_cast<const float4*>(&s_x[i * XS + (nq << 2)]);
        float4 wv = *reinterpret_cast<const float4*>(&s_w[(i << 6) + (oq << 2)]);
        acc[0][0] += xv.x * wv.x; acc[0][1] += xv.x * wv.y; acc[0][2] += xv.x * wv.z; acc[0][3] += xv.x * wv.w;
        acc[1][0] += xv.y * wv.x; acc[1][1] += xv.y * wv.y; acc[1][2] += xv.y * wv.z; acc[1][3] += xv.y * wv.w;
        acc[2][0] += xv.z * wv.x; acc[2][1] += xv.z * wv.y; acc[2][2] += xv.z * wv.z; acc[2][3] += xv.z * wv.w;
        acc[3][0] += xv.w * wv.x; acc[3][1] += xv.w * wv.y; acc[3][2] += xv.w * wv.z; acc[3][3] += xv.w * wv.w;
    }
#pragma unroll
    for (int dn = 0; dn < 4; dn++) {
        int n = n0 + (nq << 2) + dn;
        if (n < N_NODES) {
            __half2 h0 = __floats2half2_rn(acc[dn][0], acc[dn][1]);
            __half2 h1 = __floats2half2_rn(acc[dn][2], acc[dn][3]);
            uint2 pack;
            pack.x = *reinterpret_cast<uint32_t*>(&h0);
            pack.y = *reinterpret_cast<uint32_t*>(&h1);
            *reinterpret_cast<uint2*>(y + (size_t)n * 64 + (oq << 2)) = pack;
        }
    }
}

// ==================== fp2: conv2 finalize + conv3 projection ====================
// GEMM0: x2 = norm(relu?) wait: x2 = relu(norm(x1@rw2 + lb2 + agg*cinv))
// GEMM1: xp = relu(x2 @ pw3 + pb3)   GEMM2: y8(half) = xp @ lw3 ; zero agg8
__global__ __launch_bounds__(256) void fp2_kernel(const float* __restrict__ x1,
                                                  const __half* __restrict__ agg,
                                                  const float* __restrict__ cinv,
                                                  const float* __restrict__ rw2,
                                                  const float* __restrict__ lb2,
                                                  const float* __restrict__ pw3,
                                                  const float* __restrict__ pb3,
                                                  const float* __restrict__ lw3,
                                                  float* __restrict__ x2,
                                                  __half* __restrict__ y8,
                                                  float* __restrict__ agg8z) {
    constexpr int XS = 68;
    __shared__ float s_w[64 * 64];
    __shared__ float s_x[64 * XS];
    __shared__ float s_b[64];
    const int t = threadIdx.x;
    const int n0 = blockIdx.x * 64;
    const int oq = t & 15, nq = t >> 4;

    // zero agg8 slice: 64 nodes * 8 floats = 128 float4
    if (t < 128) {
        int gi = blockIdx.x * 128 + t;
        if (gi < N_NODES * 2) {
            float4 z = make_float4(0.f, 0.f, 0.f, 0.f);
            reinterpret_cast<float4*>(agg8z)[gi] = z;
        }
    }

    for (int i4 = t; i4 < 1024; i4 += 256)
        reinterpret_cast<float4*>(s_w)[i4] = reinterpret_cast<const float4*>(rw2)[i4];
    if (t < 64) s_b[t] = lb2[t];
    for (int idx = t; idx < 64 * 64; idx += 256) {
        int n = idx >> 6, i = idx & 63;
        int nn = min(n0 + n, N_NODES - 1);
        s_x[i * XS + n] = x1[(size_t)nn * 64 + i];
    }
    __syncthreads();

    // ---- GEMM0: root term ----
    float acc[4][4];
#pragma unroll
    for (int a = 0; a < 4; a++)
#pragma unroll
        for (int b = 0; b < 4; b++) acc[a][b] = 0.f;
#pragma unroll 8
    for (int i = 0; i < 64; i++) {
        float4 xv = *reinterpret_cast<const float4*>(&s_x[i * XS + (nq << 2)]);
        float4 wv = *reinterpret_cast<const float4*>(&s_w[(i << 6) + (oq << 2)]);
        acc[0][0] += xv.x * wv.x; acc[0][1] += xv.x * wv.y; acc[0][2] += xv.x * wv.z; acc[0][3] += xv.x * wv.w;
        acc[1][0] += xv.y * wv.x; acc[1][1] += xv.y * wv.y; acc[1][2] += xv.y * wv.z; acc[1][3] += xv.y * wv.w;
        acc[2][0] += xv.z * wv.x; acc[2][1] += xv.z * wv.y; acc[2][2] += xv.z * wv.z; acc[2][3] += xv.z * wv.w;
        acc[3][0] += xv.w * wv.x; acc[3][1] += xv.w * wv.y; acc[3][2] += xv.w * wv.z; acc[3][3] += xv.w * wv.w;
    }
    float lb0 = s_b[(oq << 2) + 0], lb1v = s_b[(oq << 2) + 1];
    float lb2v = s_b[(oq << 2) + 2], lb3 = s_b[(oq << 2) + 3];
#pragma unroll
    for (int dn = 0; dn < 4; dn++) {
        int n = n0 + (nq << 2) + dn;
        int nn = min(n, N_NODES - 1);
        float ci = cinv[nn];
        uint2 raw = *reinterpret_cast<const uint2*>(agg + (size_t)nn * 64 + (oq << 2));
        float2 g0 = __half22float2(*reinterpret_cast<__half2*>(&raw.x));
        float2 g1 = __half22float2(*reinterpret_cast<__half2*>(&raw.y));
        float v0 = acc[dn][0] + lb0 + g0.x * ci;
        float v1 = acc[dn][1] + lb1v + g0.y * ci;
        float v2 = acc[dn][2] + lb2v + g1.x * ci;
        float v3 = acc[dn][3] + lb3 + g1.y * ci;
        float ss = v0 * v0 + v1 * v1 + v2 * v2 + v3 * v3;
        ss += __shfl_down_sync(0xffffffffu, ss, 8, 16);
        ss += __shfl_down_sync(0xffffffffu, ss, 4, 16);
        ss += __shfl_down_sync(0xffffffffu, ss, 2, 16);
        ss += __shfl_down_sync(0xffffffffu, ss, 1, 16);
        ss = __shfl_sync(0xffffffffu, ss, 0, 16);
        float sc = 1.f / fmaxf(sqrtf(ss), EPS_NORM);
        acc[dn][0] = fmaxf(v0 * sc, 0.f);
        acc[dn][1] = fmaxf(v1 * sc, 0.f);
        acc[dn][2] = fmaxf(v2 * sc, 0.f);
        acc[dn][3] = fmaxf(v3 * sc, 0.f);
    }
    __syncthreads();

    // write x2 global + transposed into s_x
#pragma unroll
    for (int dn = 0; dn < 4; dn++) {
        int n = n0 + (nq << 2) + dn;
        if (n < N_NODES) {
            *reinterpret_cast<float4*>(&x2[(size_t)n * 64 + (oq << 2)]) =
                make_float4(acc[dn][0], acc[dn][1], acc[dn][2], acc[dn][3]);
        }
#pragma unroll
        for (int dk = 0; dk < 4; dk++)
            s_x[((oq << 2) + dk) * XS + (nq << 2) + dn] = acc[dn][dk];
    }
    for (int i4 = t; i4 < 1024; i4 += 256)
        reinterpret_cast<float4*>(s_w)[i4] = reinterpret_cast<const float4*>(pw3)[i4];
    if (t < 64) s_b[t] = pb3[t];
    __syncthreads();

    // ---- GEMM1: xp = relu(x2 @ pw3 + pb3) ----
#pragma unroll
    for (int a = 0; a < 4; a++)
#pragma unroll
        for (int b = 0; b < 4; b++) acc[a][b] = 0.f;
#pragma unroll 8
    for (int i = 0; i < 64; i++) {
        float4 xv = *reinterpret_cast<const float4*>(&s_x[i * XS + (nq << 2)]);
        float4 wv = *reinterpret_cast<const float4*>(&s_w[(i << 6) + (oq << 2)]);
        acc[0][0] += xv.x * wv.x; acc[0][1] += xv.x * wv.y; acc[0][2] += xv.x * wv.z; acc[0][3] += xv.x * wv.w;
        acc[1][0] += xv.y * wv.x; acc[1][1] += xv.y * wv.y; acc[1][2] += xv.y * wv.z; acc[1][3] += xv.y * wv.w;
        acc[2][0] += xv.z * wv.x; acc[2][1] += xv.z * wv.y; acc[2][2] += xv.z * wv.z; acc[2][3] += xv.z * wv.w;
        acc[3][0] += xv.w * wv.x; acc[3][1] += xv.w * wv.y; acc[3][2] += xv.w * wv.z; acc[3][3] += xv.w * wv.w;
    }
    __syncthreads();
#pragma unroll
    for (int dk = 0; dk < 4; dk++) {
        float b = s_b[(oq << 2) + dk];
#pragma unroll
        for (int dn = 0; dn < 4; dn++)
            s_x[((oq << 2) + dk) * XS + (nq << 2) + dn] = fmaxf(acc[dn][dk] + b, 0.f);
    }
    // load lw3 padded [64][8]
    for (int idx = t; idx < 64 * 8; idx += 256) s_w[idx] = 0.f;
    __syncthreads();
    for (int idx = t; idx < 64 * 5; idx += 256) s_w[(idx / 5) * 8 + (idx % 5)] = lw3[idx];
    __syncthreads();

    // ---- GEMM2: y8 = xp @ lw3 (OUTP=8) ----
    if (oq < 2) {
        float a2[4][4];
#pragma unroll
        for (int a = 0; a < 4; a++)
#pragma unroll
            for (int b = 0; b < 4; b++) a2[a][b] = 0.f;
#pragma unroll 8
        for (int i = 0; i < 64; i++) {
            float4 xv = *reinterpret_cast<const float4*>(&s_x[i * XS + (nq << 2)]);
            float4 wv = *reinterpret_cast<const float4*>(&s_w[i * 8 + (oq << 2)]);
            a2[0][0] += xv.x * wv.x; a2[0][1] += xv.x * wv.y; a2[0][2] += xv.x * wv.z; a2[0][3] += xv.x * wv.w;
            a2[1][0] += xv.y * wv.x; a2[1][1] += xv.y * wv.y; a2[1][2] += xv.y * wv.z; a2[1][3] += xv.y * wv.w;
            a2[2][0] += xv.z * wv.x; a2[2][1] += xv.z * wv.y; a2[2][2] += xv.z * wv.z; a2[2][3] += xv.z * wv.w;
            a2[3][0] += xv.w * wv.x; a2[3][1] += xv.w * wv.y; a2[3][2] += xv.w * wv.z; a2[3][3] += xv.w * wv.w;
        }
#pragma unroll
        for (int dn = 0; dn < 4; dn++) {
            int n = n0 + (nq << 2) + dn;
            if (n < N_NODES) {
                __half2 h0 = __floats2half2_rn(a2[dn][0], a2[dn][1]);
                __half2 h1 = __floats2half2_rn(a2[dn][2], a2[dn][3]);
                uint2 pack;
                pack.x = *reinterpret_cast<uint32_t*>(&h0);
                pack.y = *reinterpret_cast<uint32_t*>(&h1);
                *reinterpret_cast<uint2*>(y8 + (size_t)n * 8 + (oq << 2)) = pack;
            }
        }
    }
}

// ------- conv3 finalize: out5 = agg*cinv + lb + x2@rw ; norm (no relu) -------
__global__ __launch_bounds__(128) void fin3_kernel(const float* __restrict__ x2,
                                                   const float* __restrict__ agg8,
                                                   const float* __restrict__ cinv,
                                                   const float* __restrict__ rw,
                                                   const float* __restrict__ lb,
                                                   float* __restrict__ out) {
    __shared__ float s_rw[64 * 8];
    __shared__ float s_lb[8];
    int t = threadIdx.x;
    for (int idx = t; idx < 320; idx += 128) s_rw[(idx / 5) * 8 + (idx % 5)] = rw[idx];
    if (t < 5) s_lb[t] = lb[t];
    __syncthreads();
    int n = blockIdx.x * 128 + t;
    if (n >= N_NODES) return;

    float ci = cinv[n];
    const float4* av = reinterpret_cast<const float4*>(agg8 + (size_t)n * 8);
    float4 a0 = av[0], a1 = av[1];
    float4 vf = make_float4(s_lb[0] + a0.x * ci, s_lb[1] + a0.y * ci,
                            s_lb[2] + a0.z * ci, s_lb[3] + a0.w * ci);
    float v4 = s_lb[4] + a1.x * ci;

    const float4* xr = reinterpret_cast<const float4*>(x2 + (size_t)n * 64);
#pragma unroll
    for (int iq = 0; iq < 16; iq++) {
        float4 xv = xr[iq];
        float xs[4] = {xv.x, xv.y, xv.z, xv.w};
#pragma unroll
        for (int c = 0; c < 4; c++) {
            int i = iq * 4 + c;
            float4 w = *reinterpret_cast<const float4*>(&s_rw[i * 8]);
            float w4 = s_rw[i * 8 + 4];
            vf.x += xs[c] * w.x;
            vf.y += xs[c] * w.y;
            vf.z += xs[c] * w.z;
            vf.w += xs[c] * w.w;
            v4 += xs[c] * w4;
        }
    }
    float ss = vf.x * vf.x + vf.y * vf.y + vf.z * vf.z + vf.w * vf.w + v4 * v4;
    float sc = 1.f / fmaxf(sqrtf(ss), EPS_NORM);
    float* o = out + (size_t)n * 5;
    o[0] = vf.x * sc;
    o[1] = vf.y * sc;
    o[2] = vf.z * sc;
    o[3] = vf.w * sc;
    o[4] = v4 * sc;
}

// ---------------- host launcher ----------------
extern "C" void kernel_launch(void* const* d_in, const int* in_sizes, int n_in,
                              void* d_out, int out_size) {
    const float* h = (const float*)d_in[0];
    const int* ei = (const int*)d_in[1];
    const float* ew = (const float*)d_in[2];
    const float* gamma = (const float*)d_in[3];
    const float* beta = (const float*)d_in[4];
    const float* c1_pw = (const float*)d_in[5];
    const float* c1_pb = (const float*)d_in[6];
    const float* c1_lw = (const float*)d_in[7];
    const float* c1_lb = (const float*)d_in[8];
    const float* c1_rw = (const float*)d_in[9];
    const float* c2_pw = (const float*)d_in[10];
    const float* c2_pb = (const float*)d_in[11];
    const float* c2_lw = (const float*)d_in[12];
    const float* c2_lb = (const float*)d_in[13];
    const float* c2_rw = (const float*)d_in[14];
    const float* c3_pw = (const float*)d_in[15];
    const float* c3_pb = (const float*)d_in[16];
    const float* c3_lw = (const float*)d_in[17];
    const float* c3_lb = (const float*)d_in[18];
    const float* c3_rw = (const float*)d_in[19];
    float* out = (float*)d_out;

    const int* src = ei;
    const int* dst = ei + N_EDGES;

    float *x0, *x1, *x2, *agg8, *cinv, *part;
    __half *yh, *aggh;
    cudaGetSymbolAddress((void**)&x0, g_x0);
    cudaGetSymbolAddress((void**)&x1, g_x1);
    cudaGetSymbolAddress((void**)&x2, g_x2);
    cudaGetSymbolAddress((void**)&yh, g_yh);
    cudaGetSymbolAddress((void**)&aggh, g_aggh);
    cudaGetSymbolAddress((void**)&agg8, g_agg8);
    cudaGetSymbolAddress((void**)&cinv, g_cinv);
    cudaGetSymbolAddress((void**)&part, g_part);

    const int NB64 = (N_NODES + 63) / 64;   // 1563

    // 1: BN partial stats
    bn_stats_kernel<<<148, 256>>>(h, part);
    // 2: BN apply + conv1 5x5 projection (fp16 y8); zeroes agg8
    bn_conv1_kernel<<<(N_NODES + 255) / 256, 256>>>(h, part, gamma, beta, c1_pw, c1_pb,
                                                    x0, yh, agg8);
    // 3: conv1 push-scatter (width 5 + cnt)
    scatter8_kernel<true><<<6250, 256>>>(src, dst, ew, yh, agg8);
    // 4: FUSED conv1-finalize + conv2-projection (zeroes aggh) — CAPTURED BY NCU
    fp1_kernel<<<NB64, 256>>>(x0, agg8, c1_lw, c1_lb, c1_rw,
                              c2_pw, c2_pb, c2_lw, x1, cinv, yh, aggh);
    // 5: conv2 push-scatter (fp16 atomics)
    scatter64_kernel<<<4096, 256>>>(src, dst, ew, yh, aggh);
    // 6: FUSED conv2-finalize + conv3-projection (zeroes agg8)
    fp2_kernel<<<NB64, 256>>>(x1, aggh, cinv, c2_rw, c2_lb,
                              c3_pw, c3_pb, c3_lw, x2, yh, agg8);
    // 7: conv3 push-scatter (width 5)
    scatter8_kernel<false><<<6250, 256>>>(src, dst, ew, yh, agg8);
    // 8: conv3 finalize
    fin3_kernel<<<(N_NODES + 127) / 128, 128>>>(x2, agg8, cinv, c3_rw, c3_lb, out);
}

// round 11
// speedup vs baseline: 1.6828x; 1.0366x over previous
#include <cuda_runtime.h>
#include <cuda_fp16.h>
#include <cstdint>
#include <math.h>

#define N_NODES 100000
#define N_EDGES 3200000
#define EPS_BN 1e-5f
#define EPS_NORM 1e-12f

// ---------------- device scratch (no allocation allowed) ----------------
__device__ __align__(16) float g_x0[N_NODES * 8];     // BN output (padded stride 8)
__device__ __align__(16) float g_x1[N_NODES * 64];    // conv1 output
__device__ __align__(16) float g_x2[N_NODES * 64];    // conv2 output
__device__ __align__(16) __half g_yh[N_NODES * 64];   // fp16 projected features (stride 64 or 8)
__device__ __align__(16) __half g_aggh[N_NODES * 64]; // conv2 accumulator (fp16 atomics)
__device__ __align__(32) float g_agg8[N_NODES * 8];   // conv1/conv3 accumulator (5 feats + cnt)
__device__ float g_cinv[N_NODES];                     // 1/max(cnt,1)
__device__ __align__(16) float g_part[148 * 16];      // BN per-block partials

// ---------------- vector reductions ----------------
__device__ __forceinline__ void red_add_v4(float* p, float4 v) {
    asm volatile("red.global.add.v4.f32 [%0], {%1,%2,%3,%4};"
                 :: "l"(p), "f"(v.x), "f"(v.y), "f"(v.z), "f"(v.w) : "memory");
}
__device__ __forceinline__ void red_add_v2(float* p, float a, float b) {
    asm volatile("red.global.add.v2.f32 [%0], {%1,%2};"
                 :: "l"(p), "f"(a), "f"(b) : "memory");
}
__device__ __forceinline__ void red_add_f32(float* p, float a) {
    asm volatile("red.global.add.f32 [%0], %1;"
                 :: "l"(p), "f"(a) : "memory");
}
__device__ __forceinline__ void red_add_v2_h2(__half* p, uint32_t a, uint32_t b) {
    asm volatile("red.global.add.noftz.v2.f16x2 [%0], {%1,%2};"
                 :: "l"(p), "r"(a), "r"(b) : "memory");
}

// ---------------- packed f32x2 FMA helpers ----------------
__device__ __forceinline__ unsigned long long pack2(float v) {
    unsigned long long r;
    asm("mov.b64 %0, {%1, %1};" : "=l"(r) : "f"(v));
    return r;
}
__device__ __forceinline__ unsigned long long fma2(unsigned long long a,
                                                   unsigned long long b,
                                                   unsigned long long c) {
    unsigned long long d;
    asm("fma.rn.f32x2 %0, %1, %2, %3;" : "=l"(d) : "l"(a), "l"(b), "l"(c));
    return d;
}
__device__ __forceinline__ void unpack2(unsigned long long p, float& lo, float& hi) {
    asm("mov.b64 {%0, %1}, %2;" : "=f"(lo), "=f"(hi) : "l"(p));
}

// swizzled column-group: physical cg = cg ^ ((row>>2)&15); row stride 64 floats
__device__ __forceinline__ int swidx(int row, int cg, int c) {
    return (row << 6) + (((cg ^ ((row >> 2) & 15)) & 15) << 2) + c;
}

// ---- K=64 GEMM via f32x2: acc[node 0..3][out 0..3], x swizzled [feat][node] ----
__device__ __forceinline__ void gemm64_fx2(const float* __restrict__ s_x,
                                           const float* __restrict__ s_w,
                                           int oq, int nq, float acc[4][4]) {
    unsigned long long a2[2][4];
#pragma unroll
    for (int p = 0; p < 2; p++)
#pragma unroll
        for (int k = 0; k < 4; k++) a2[p][k] = 0ull;
#pragma unroll 8
    for (int i = 0; i < 64; i++) {
        ulonglong2 xp = *reinterpret_cast<const ulonglong2*>(
            &s_x[(i << 6) + (((nq ^ ((i >> 2) & 15)) & 15) << 2)]);
        float4 wv = *reinterpret_cast<const float4*>(&s_w[(i << 6) + (oq << 2)]);
        unsigned long long w0 = pack2(wv.x), w1 = pack2(wv.y);
        unsigned long long w2 = pack2(wv.z), w3 = pack2(wv.w);
        a2[0][0] = fma2(xp.x, w0, a2[0][0]);
        a2[0][1] = fma2(xp.x, w1, a2[0][1]);
        a2[0][2] = fma2(xp.x, w2, a2[0][2]);
        a2[0][3] = fma2(xp.x, w3, a2[0][3]);
        a2[1][0] = fma2(xp.y, w0, a2[1][0]);
        a2[1][1] = fma2(xp.y, w1, a2[1][1]);
        a2[1][2] = fma2(xp.y, w2, a2[1][2]);
        a2[1][3] = fma2(xp.y, w3, a2[1][3]);
    }
#pragma unroll
    for (int k = 0; k < 4; k++) {
        unpack2(a2[0][k], acc[0][k], acc[1][k]);
        unpack2(a2[1][k], acc[2][k], acc[3][k]);
    }
}

// ------- BatchNorm statistics: per-block partials (no pre-zeroing) -------
__global__ __launch_bounds__(256) void bn_stats_kernel(const float* __restrict__ h,
                                                       float* __restrict__ part) {
    float s[5] = {0, 0, 0, 0, 0}, q[5] = {0, 0, 0, 0, 0};
    int stride = gridDim.x * blockDim.x;
    for (int n = blockIdx.x * blockDim.x + threadIdx.x; n < N_NODES; n += stride) {
#pragma unroll
        for (int i = 0; i < 5; i++) {
            float v = h[n * 5 + i];
            s[i] += v;
            q[i] += v * v;
        }
    }
#pragma unroll
    for (int k = 16; k > 0; k >>= 1) {
#pragma unroll
        for (int i = 0; i < 5; i++) {
            s[i] += __shfl_down_sync(0xffffffffu, s[i], k);
            q[i] += __shfl_down_sync(0xffffffffu, q[i], k);
        }
    }
    __shared__ float sh[10];
    if (threadIdx.x < 10) sh[threadIdx.x] = 0.f;
    __syncthreads();
    if ((threadIdx.x & 31) == 0) {
#pragma unroll
        for (int i = 0; i < 5; i++) {
            atomicAdd(&sh[i], s[i]);
            atomicAdd(&sh[5 + i], q[i]);
        }
    }
    __syncthreads();
    if (threadIdx.x < 10) part[blockIdx.x * 16 + threadIdx.x] = sh[threadIdx.x];
}

// ------- BN apply + conv1 projection (5x5) -> fp16 y8 ; zero agg8 -------
__global__ __launch_bounds__(256) void bn_conv1_kernel(const float* __restrict__ h,
                                                       const float* __restrict__ part,
                                                       const float* __restrict__ gamma,
                                                       const float* __restrict__ beta,
                                                       const float* __restrict__ pw,
                                                       const float* __restrict__ pb,
                                                       float* __restrict__ x0p,
                                                       __half* __restrict__ y8,
                                                       float* __restrict__ agg8) {
    __shared__ float s_warp[8][10];
    __shared__ float s_stats[10];
    int t = threadIdx.x;
    int lane = t & 31, wid = t >> 5;
    {
        float v[10];
#pragma unroll
        for (int i = 0; i < 10; i++) v[i] = 0.f;
        if (t < 148) {
#pragma unroll
            for (int i = 0; i < 10; i++) v[i] = part[t * 16 + i];
        }
#pragma unroll
        for (int k = 16; k > 0; k >>= 1) {
#pragma unroll
            for (int i = 0; i < 10; i++) v[i] += __shfl_down_sync(0xffffffffu, v[i], k);
        }
        if (lane == 0) {
#pragma unroll
            for (int i = 0; i < 10; i++) s_warp[wid][i] = v[i];
        }
    }
    __syncthreads();
    if (t < 10) {
        float acc = 0.f;
#pragma unroll
        for (int w = 0; w < 8; w++) acc += s_warp[w][t];
        s_stats[t] = acc;
    }
    __syncthreads();

    int n = blockIdx.x * blockDim.x + t;
    if (n >= N_NODES) return;
    const float inv_n = 1.f / (float)N_NODES;
    float xr[5];
#pragma unroll
    for (int i = 0; i < 5; i++) {
        float mu = s_stats[i] * inv_n;
        float var = s_stats[5 + i] * inv_n - mu * mu;
        float sc = rsqrtf(var + EPS_BN) * gamma[i];
        xr[i] = (h[n * 5 + i] - mu) * sc + beta[i];
    }
    float4* x0v = reinterpret_cast<float4*>(x0p + (size_t)n * 8);
    x0v[0] = make_float4(xr[0], xr[1], xr[2], xr[3]);
    x0v[1] = make_float4(xr[4], 0.f, 0.f, 0.f);
    float xp[5];
#pragma unroll
    for (int k = 0; k < 5; k++) {
        float v = pb[k];
#pragma unroll
        for (int i = 0; i < 5; i++) v += xr[i] * pw[i * 5 + k];
        xp[k] = fmaxf(v, 0.f);
    }
    __half2 h0 = __floats2half2_rn(xp[0], xp[1]);
    __half2 h1 = __floats2half2_rn(xp[2], xp[3]);
    __half2 h2 = __floats2half2_rn(xp[4], 0.f);
    uint4 pack;
    pack.x = *reinterpret_cast<uint32_t*>(&h0);
    pack.y = *reinterpret_cast<uint32_t*>(&h1);
    pack.z = *reinterpret_cast<uint32_t*>(&h2);
    pack.w = 0u;
    *reinterpret_cast<uint4*>(y8 + (size_t)n * 8) = pack;
    float4* av = reinterpret_cast<float4*>(agg8 + (size_t)n * 8);
    float4 z = make_float4(0.f, 0.f, 0.f, 0.f);
    av[0] = z;
    av[1] = z;
}

// -------- width-8 push scatter (one edge per thread) --------
template <bool ADD_CNT>
__global__ void scatter8_kernel(const int* __restrict__ src,
                                const int* __restrict__ dst,
                                const float* __restrict__ ew,
                                const __half* __restrict__ y8,
                                float* __restrict__ agg8) {
    int stride = gridDim.x * blockDim.x;
    for (int e = blockIdx.x * blockDim.x + threadIdx.x; e < N_EDGES; e += stride) {
        int s = __ldg(&src[e]);
        int d = __ldg(&dst[e]);
        float w = __ldg(&ew[e]);
        uint4 raw = *reinterpret_cast<const uint4*>(y8 + (size_t)s * 8);
        float2 f0 = __half22float2(*reinterpret_cast<__half2*>(&raw.x));
        float2 f1 = __half22float2(*reinterpret_cast<__half2*>(&raw.y));
        float2 f2 = __half22float2(*reinterpret_cast<__half2*>(&raw.z));
        red_add_v4(agg8 + (size_t)d * 8,
                   make_float4(f0.x * w, f0.y * w, f1.x * w, f1.y * w));
        if (ADD_CNT)
            red_add_v2(agg8 + (size_t)d * 8 + 4, f2.x * w, 1.0f);
        else
            red_add_f32(agg8 + (size_t)d * 8 + 4, f2.x * w);
    }
}

// -------- width-64 push scatter: fp16 reads AND fp16 atomics --------
__global__ void scatter64_kernel(const int* __restrict__ src,
                                 const int* __restrict__ dst,
                                 const float* __restrict__ ew,
                                 const __half* __restrict__ y,
                                 __half* __restrict__ agg) {
    int lane = threadIdx.x & 31;
    int warp = (blockIdx.x * blockDim.x + threadIdx.x) >> 5;
    int nwarps = (gridDim.x * blockDim.x) >> 5;
    int half = lane >> 4;
    int fq = (lane & 15) << 2;
    const int npairs = N_EDGES / 2;
    for (int p = warp; p < npairs; p += nwarps) {
        int e = 2 * p + half;
        int s = __ldg(&src[e]);
        int d = __ldg(&dst[e]);
        float w = __ldg(&ew[e]);
        uint2 raw = *reinterpret_cast<const uint2*>(y + (size_t)s * 64 + fq);
        float2 f0 = __half22float2(*reinterpret_cast<__half2*>(&raw.x));
        float2 f1 = __half22float2(*reinterpret_cast<__half2*>(&raw.y));
        __half2 h0 = __floats2half2_rn(f0.x * w, f0.y * w);
        __half2 h1 = __floats2half2_rn(f1.x * w, f1.y * w);
        red_add_v2_h2(agg + (size_t)d * 64 + fq,
                      *reinterpret_cast<uint32_t*>(&h0),
                      *reinterpret_cast<uint32_t*>(&h1));
    }
}

// ==================== fp1: conv1 finalize + conv2 projection ====================
__global__ __launch_bounds__(256) void fp1_kernel(const float* __restrict__ x0p,
                                                  const float* __restrict__ agg8,
                                                  const float* __restrict__ lw1,
                                                  const float* __restrict__ lb1,
                                                  const float* __restrict__ rw1,
                                                  const float* __restrict__ pw2,
                                                  const float* __restrict__ pb2,
                                                  const float* __restrict__ lw2,
                                                  float* __restrict__ x1,
                                                  float* __restrict__ cinv_out,
                                                  __half* __restrict__ y,
                                                  __half* __restrict__ aggh_zero) {
    __shared__ float s_w[64 * 64];
    __shared__ float s_x[64 * 64];
    __shared__ float s_b[64];
    __shared__ float s_ci[64];
    const int t = threadIdx.x;
    const int n0 = blockIdx.x * 64;
    const int oq = t & 15, nq = t >> 4;

    // zero aggh slice: 64 nodes * 64 halves = 512 float4
    {
        float4 z = make_float4(0.f, 0.f, 0.f, 0.f);
        float4* zb = reinterpret_cast<float4*>(aggh_zero);
        int base = blockIdx.x * 512;
        for (int i = t; i < 512; i += 256) {
            int gi = base + i;
            if (gi < N_NODES * 8) zb[gi] = z;
        }
    }

    // ---- stage GEMM0 operands (K=10, row stride 72 in s_x front) ----
    for (int idx = t; idx < 640; idx += 256)
        s_w[idx] = (idx < 320) ? lw1[idx] : rw1[idx - 320];
    if (t < 64) s_b[t] = lb1[t];
    if (t < 64) {
        int nn = min(n0 + t, N_NODES - 1);
        float c = agg8[(size_t)nn * 8 + 5];
        float ci = 1.f / fmaxf(c, 1.f);
        s_ci[t] = ci;
        if (n0 + t < N_NODES) cinv_out[n0 + t] = ci;
    }
    __syncthreads();
    for (int idx = t; idx < 640; idx += 256) {
        int i = idx >> 6, nd = idx & 63;
        int nn = min(n0 + nd, N_NODES - 1);
        s_x[i * 72 + nd] = (i < 5) ? agg8[(size_t)nn * 8 + i] * s_ci[nd]
                                   : x0p[(size_t)nn * 8 + (i - 5)];
    }
    __syncthreads();

    // ---- GEMM0: K=10 (scalar) ----
    float acc[4][4];
#pragma unroll
    for (int a = 0; a < 4; a++)
#pragma unroll
        for (int b = 0; b < 4; b++) acc[a][b] = 0.f;
#pragma unroll
    for (int i = 0; i < 10; i++) {
        float4 xv = *reinterpret_cast<const float4*>(&s_x[i * 72 + (nq << 2)]);
        float4 wv = *reinterpret_cast<const float4*>(&s_w[(i << 6) + (oq << 2)]);
        acc[0][0] += xv.x * wv.x; acc[0][1] += xv.x * wv.y; acc[0][2] += xv.x * wv.z; acc[0][3] += xv.x * wv.w;
        acc[1][0] += xv.y * wv.x; acc[1][1] += xv.y * wv.y; acc[1][2] += xv.y * wv.z; acc[1][3] += xv.y * wv.w;
        acc[2][0] += xv.z * wv.x; acc[2][1] += xv.z * wv.y; acc[2][2] += xv.z * wv.z; acc[2][3] += xv.z * wv.w;
        acc[3][0] += xv.w * wv.x; acc[3][1] += xv.w * wv.y; acc[3][2] += xv.w * wv.z; acc[3][3] += xv.w * wv.w;
    }
    float lb0 = s_b[(oq << 2) + 0], lb1v = s_b[(oq << 2) + 1];
    float lb2 = s_b[(oq << 2) + 2], lb3 = s_b[(oq << 2) + 3];
#pragma unroll
    for (int dn = 0; dn < 4; dn++) {
        float v0 = acc[dn][0] + lb0;
        float v1 = acc[dn][1] + lb1v;
        float v2 = acc[dn][2] + lb2;
        float v3 = acc[dn][3] + lb3;
        float ss = v0 * v0 + v1 * v1 + v2 * v2 + v3 * v3;
        ss += __shfl_down_sync(0xffffffffu, ss, 8, 16);
        ss += __shfl_down_sync(0xffffffffu, ss, 4, 16);
        ss += __shfl_down_sync(0xffffffffu, ss, 2, 16);
        ss += __shfl_down_sync(0xffffffffu, ss, 1, 16);
        ss = __shfl_sync(0xffffffffu, ss, 0, 16);
        float sc = 1.f / fmaxf(sqrtf(ss), EPS_NORM);
        acc[dn][0] = fmaxf(v0 * sc, 0.f);
        acc[dn][1] = fmaxf(v1 * sc, 0.f);
        acc[dn][2] = fmaxf(v2 * sc, 0.f);
        acc[dn][3] = fmaxf(v3 * sc, 0.f);
    }
    __syncthreads();

    // write x1 global + transposed (swizzled) into s_x
#pragma unroll
    for (int dn = 0; dn < 4; dn++) {
        int n = n0 + (nq << 2) + dn;
        if (n < N_NODES) {
            *reinterpret_cast<float4*>(&x1[(size_t)n * 64 + (oq << 2)]) =
                make_float4(acc[dn][0], acc[dn][1], acc[dn][2], acc[dn][3]);
        }
#pragma unroll
        for (int dk = 0; dk < 4; dk++)
            s_x[swidx((oq << 2) + dk, nq, dn)] = acc[dn][dk];
    }
    for (int i4 = t; i4 < 1024; i4 += 256)
        reinterpret_cast<float4*>(s_w)[i4] = reinterpret_cast<const float4*>(pw2)[i4];
    if (t < 64) s_b[t] = pb2[t];
    __syncthreads();

    // ---- GEMM1: K=64 (f32x2) ----
    gemm64_fx2(s_x, s_w, oq, nq, acc);
    __syncthreads();
#pragma unroll
    for (int dk = 0; dk < 4; dk++) {
        float b = s_b[(oq << 2) + dk];
#pragma unroll
        for (int dn = 0; dn < 4; dn++)
            s_x[swidx((oq << 2) + dk, nq, dn)] = fmaxf(acc[dn][dk] + b, 0.f);
    }
    for (int i4 = t; i4 < 1024; i4 += 256)
        reinterpret_cast<float4*>(s_w)[i4] = reinterpret_cast<const float4*>(lw2)[i4];
    __syncthreads();

    // ---- GEMM2: K=64 (f32x2) -> y fp16 ----
    gemm64_fx2(s_x, s_w, oq, nq, acc);
#pragma unroll
    for (int dn = 0; dn < 4; dn++) {
        int n = n0 + (nq << 2) + dn;
        if (n < N_NODES) {
            __half2 h0 = __floats2half2_rn(acc[dn][0], acc[dn][1]);
            __half2 h1 = __floats2half2_rn(acc[dn][2], acc[dn][3]);
            uint2 pack;
            pack.x = *reinterpret_cast<uint32_t*>(&h0);
            pack.y = *reinterpret_cast<uint32_t*>(&h1);
            *reinterpret_cast<uint2*>(y + (size_t)n * 64 + (oq << 2)) = pack;
        }
    }
}

// ==================== fp2: conv2 finalize + conv3 projection ====================
__global__ __launch_bounds__(256) void fp2_kernel(const float* __restrict__ x1,
                                                  const __half* __restrict__ agg,
                                                  const float* __restrict__ cinv,
                                                  const float* __restrict__ rw2,
                                                  const float* __restrict__ lb2,
                                                  const float* __restrict__ pw3,
                                                  const float* __restrict__ pb3,
                                                  const float* __restrict__ lw3,
                                                  float* __restrict__ x2,
                                                  __half* __restrict__ y8,
                                                  float* __restrict__ agg8z) {
    __shared__ float s_w[64 * 64];
    __shared__ float s_x[64 * 64];
    __shared__ float s_b[64];
    const int t = threadIdx.x;
    const int n0 = blockIdx.x * 64;
    const int oq = t & 15, nq = t >> 4;

    if (t < 128) {
        int gi = blockIdx.x * 128 + t;
        if (gi < N_NODES * 2) {
            float4 z = make_float4(0.f, 0.f, 0.f, 0.f);
            reinterpret_cast<float4*>(agg8z)[gi] = z;
        }
    }

    for (int i4 = t; i4 < 1024; i4 += 256)
        reinterpret_cast<float4*>(s_w)[i4] = reinterpret_cast<const float4*>(rw2)[i4];
    if (t < 64) s_b[t] = lb2[t];
    for (int idx = t; idx < 64 * 64; idx += 256) {
        int n = idx >> 6, i = idx & 63;
        int nn = min(n0 + n, N_NODES - 1);
        s_x[swidx(i, n >> 2, n & 3)] = x1[(size_t)nn * 64 + i];
    }
    __syncthreads();

    // ---- GEMM0: root term (f32x2) ----
    float acc[4][4];
    gemm64_fx2(s_x, s_w, oq, nq, acc);

    float lb0 = s_b[(oq << 2) + 0], lb1v = s_b[(oq << 2) + 1];
    float lb2v = s_b[(oq << 2) + 2], lb3 = s_b[(oq << 2) + 3];
#pragma unroll
    for (int dn = 0; dn < 4; dn++) {
        int n = n0 + (nq << 2) + dn;
        int nn = min(n, N_NODES - 1);
        float ci = cinv[nn];
        uint2 raw = *reinterpret_cast<const uint2*>(agg + (size_t)nn * 64 + (oq << 2));
        float2 g0 = __half22float2(*reinterpret_cast<__half2*>(&raw.x));
        float2 g1 = __half22float2(*reinterpret_cast<__half2*>(&raw.y));
        float v0 = acc[dn][0] + lb0 + g0.x * ci;
        float v1 = acc[dn][1] + lb1v + g0.y * ci;
        float v2 = acc[dn][2] + lb2v + g1.x * ci;
        float v3 = acc[dn][3] + lb3 + g1.y * ci;
        float ss = v0 * v0 + v1 * v1 + v2 * v2 + v3 * v3;
        ss += __shfl_down_sync(0xffffffffu, ss, 8, 16);
        ss += __shfl_down_sync(0xffffffffu, ss, 4, 16);
        ss += __shfl_down_sync(0xffffffffu, ss, 2, 16);
        ss += __shfl_down_sync(0xffffffffu, ss, 1, 16);
        ss = __shfl_sync(0xffffffffu, ss, 0, 16);
        float sc = 1.f / fmaxf(sqrtf(ss), EPS_NORM);
        acc[dn][0] = fmaxf(v0 * sc, 0.f);
        acc[dn][1] = fmaxf(v1 * sc, 0.f);
        acc[dn][2] = fmaxf(v2 * sc, 0.f);
        acc[dn][3] = fmaxf(v3 * sc, 0.f);
    }
    __syncthreads();

    // write x2 global + transposed (swizzled)
#pragma unroll
    for (int dn = 0; dn < 4; dn++) {
        int n = n0 + (nq << 2) + dn;
        if (n < N_NODES) {
            *reinterpret_cast<float4*>(&x2[(size_t)n * 64 + (oq << 2)]) =
                make_float4(acc[dn][0], acc[dn][1], acc[dn][2], acc[dn][3]);
        }
#pragma unroll
        for (int dk = 0; dk < 4; dk++)
            s_x[swidx((oq << 2) + dk, nq, dn)] = acc[dn][dk];
    }
    for (int i4 = t; i4 < 1024; i4 += 256)
        reinterpret_cast<float4*>(s_w)[i4] = reinterpret_cast<const float4*>(pw3)[i4];
    if (t < 64) s_b[t] = pb3[t];
    __syncthreads();

    // ---- GEMM1: xp = relu(x2 @ pw3 + pb3) (f32x2) ----
    gemm64_fx2(s_x, s_w, oq, nq, acc);
    __syncthreads();
#pragma unroll
    for (int dk = 0; dk < 4; dk++) {
        float b = s_b[(oq << 2) + dk];
#pragma unroll
        for (int dn = 0; dn < 4; dn++)
            s_x[swidx((oq << 2) + dk, nq, dn)] = fmaxf(acc[dn][dk] + b, 0.f);
    }
    for (int idx = t; idx < 64 * 8; idx += 256) s_w[idx] = 0.f;
    __syncthreads();
    for (int idx = t; idx < 64 * 5; idx += 256) s_w[(idx / 5) * 8 + (idx % 5)] = lw3[idx];
    __syncthreads();

    // ---- GEMM2: y8 = xp @ lw3 (OUTP=8, scalar, swizzled x loads) ----
    if (oq < 2) {
        float a2[4][4];
#pragma unroll
        for (int a = 0; a < 4; a++)
#pragma unroll
            for (int b = 0; b < 4; b++) a2[a][b] = 0.f;
#pragma unroll 8
        for (int i = 0; i < 64; i++) {
            float4 xv = *reinterpret_cast<const float4*>(
                &s_x[(i << 6) + (((nq ^ ((i >> 2) & 15)) & 15) << 2)]);
            float4 wv = *reinterpret_cast<const float4*>(&s_w[i * 8 + (oq << 2)]);
            a2[0][0] += xv.x * wv.x; a2[0][1] += xv.x * wv.y; a2[0][2] += xv.x * wv.z; a2[0][3] += xv.x * wv.w;
            a2[1][0] += xv.y * wv.x; a2[1][1] += xv.y * wv.y; a2[1][2] += xv.y * wv.z; a2[1][3] += xv.y * wv.w;
            a2[2][0] += xv.z * wv.x; a2[2][1] += xv.z * wv.y; a2[2][2] += xv.z * wv.z; a2[2][3] += xv.z * wv.w;
            a2[3][0] += xv.w * wv.x; a2[3][1] += xv.w * wv.y; a2[3][2] += xv.w * wv.z; a2[3][3] += xv.w * wv.w;
        }
#pragma unroll
        for (int dn = 0; dn < 4; dn++) {
            int n = n0 + (nq << 2) + dn;
            if (n < N_NODES) {
                __half2 h0 = __floats2half2_rn(a2[dn][0], a2[dn][1]);
                __half2 h1 = __floats2half2_rn(a2[dn][2], a2[dn][3]);
                uint2 pack;
                pack.x = *reinterpret_cast<uint32_t*>(&h0);
                pack.y = *reinterpret_cast<uint32_t*>(&h1);
                *reinterpret_cast<uint2*>(y8 + (size_t)n * 8 + (oq << 2)) = pack;
            }
        }
    }
}

// ------- conv3 finalize: out5 = agg*cinv + lb + x2@rw ; norm (no relu) -------
__global__ __launch_bounds__(128) void fin3_kernel(const float* __restrict__ x2,
                                                   const float* __restrict__ agg8,
                                                   const float* __restrict__ cinv,
                                                   const float* __restrict__ rw,
                                                   const float* __restrict__ lb,
                                                   float* __restrict__ out) {
    __shared__ float s_rw[64 * 8];
    __shared__ float s_lb[8];
    int t = threadIdx.x;
    for (int idx = t; idx < 320; idx += 128) s_rw[(idx / 5) * 8 + (idx % 5)] = rw[idx];
    if (t < 5) s_lb[t] = lb[t];
    __syncthreads();
    int n = blockIdx.x * 128 + t;
    if (n >= N_NODES) return;

    float ci = cinv[n];
    const float4* av = reinterpret_cast<const float4*>(agg8 + (size_t)n * 8);
    float4 a0 = av[0], a1 = av[1];
    float4 vf = make_float4(s_lb[0] + a0.x * ci, s_lb[1] + a0.y * ci,
                            s_lb[2] + a0.z * ci, s_lb[3] + a0.w * ci);
    float v4 = s_lb[4] + a1.x * ci;

    const float4* xr = reinterpret_cast<const float4*>(x2 + (size_t)n * 64);
#pragma unroll
    for (int iq = 0; iq < 16; iq++) {
        float4 xv = xr[iq];
        float xs[4] = {xv.x, xv.y, xv.z, xv.w};
#pragma unroll
        for (int c = 0; c < 4; c++) {
            int i = iq * 4 + c;
            float4 w = *reinterpret_cast<const float4*>(&s_rw[i * 8]);
            float w4 = s_rw[i * 8 + 4];
            vf.x += xs[c] * w.x;
            vf.y += xs[c] * w.y;
            vf.z += xs[c] * w.z;
            vf.w += xs[c] * w.w;
            v4 += xs[c] * w4;
        }
    }
    float ss = vf.x * vf.x + vf.y * vf.y + vf.z * vf.z + vf.w * vf.w + v4 * v4;
    float sc = 1.f / fmaxf(sqrtf(ss), EPS_NORM);
    float* o = out + (size_t)n * 5;
    o[0] = vf.x * sc;
    o[1] = vf.y * sc;
    o[2] = vf.z * sc;
    o[3] = vf.w * sc;
    o[4] = v4 * sc;
}

// ---------------- host launcher ----------------
extern "C" void kernel_launch(void* const* d_in, const int* in_sizes, int n_in,
                              void* d_out, int out_size) {
    const float* h = (const float*)d_in[0];
    const int* ei = (const int*)d_in[1];
    const float* ew = (const float*)d_in[2];
    const float* gamma = (const float*)d_in[3];
    const float* beta = (const float*)d_in[4];
    const float* c1_pw = (const float*)d_in[5];
    const float* c1_pb = (const float*)d_in[6];
    const float* c1_lw = (const float*)d_in[7];
    const float* c1_lb = (const float*)d_in[8];
    const float* c1_rw = (const float*)d_in[9];
    const float* c2_pw = (const float*)d_in[10];
    const float* c2_pb = (const float*)d_in[11];
    const float* c2_lw = (const float*)d_in[12];
    const float* c2_lb = (const float*)d_in[13];
    const float* c2_rw = (const float*)d_in[14];
    const float* c3_pw = (const float*)d_in[15];
    const float* c3_pb = (const float*)d_in[16];
    const float* c3_lw = (const float*)d_in[17];
    const float* c3_lb = (const float*)d_in[18];
    const float* c3_rw = (const float*)d_in[19];
    float* out = (float*)d_out;

    const int* src = ei;
    const int* dst = ei + N_EDGES;

    float *x0, *x1, *x2, *agg8, *cinv, *part;
    __half *yh, *aggh;
    cudaGetSymbolAddress((void**)&x0, g_x0);
    cudaGetSymbolAddress((void**)&x1, g_x1);
    cudaGetSymbolAddress((void**)&x2, g_x2);
    cudaGetSymbolAddress((void**)&yh, g_yh);
    cudaGetSymbolAddress((void**)&aggh, g_aggh);
    cudaGetSymbolAddress((void**)&agg8, g_agg8);
    cudaGetSymbolAddress((void**)&cinv, g_cinv);
    cudaGetSymbolAddress((void**)&part, g_part);

    const int NB64 = (N_NODES + 63) / 64;   // 1563

    // 1: BN partial stats
    bn_stats_kernel<<<148, 256>>>(h, part);
    // 2: BN apply + conv1 5x5 projection (fp16 y8); zeroes agg8
    bn_conv1_kernel<<<(N_NODES + 255) / 256, 256>>>(h, part, gamma, beta, c1_pw, c1_pb,
                                                    x0, yh, agg8);
    // 3: conv1 push-scatter (width 5 + cnt)
    scatter8_kernel<true><<<6250, 256>>>(src, dst, ew, yh, agg8);
    // 4: FUSED conv1-finalize + conv2-projection (f32x2 + swizzle) — CAPTURED BY NCU
    fp1_kernel<<<NB64, 256>>>(x0, agg8, c1_lw, c1_lb, c1_rw,
                              c2_pw, c2_pb, c2_lw, x1, cinv, yh, aggh);
    // 5: conv2 push-scatter (fp16 atomics)
    scatter64_kernel<<<4096, 256>>>(src, dst, ew, yh, aggh);
    // 6: FUSED conv2-finalize + conv3-projection (f32x2 + swizzle)
    fp2_kernel<<<NB64, 256>>>(x1, aggh, cinv, c2_rw, c2_lb,
                              c3_pw, c3_pb, c3_lw, x2, yh, agg8);
    // 7: conv3 push-scatter (width 5)
    scatter8_kernel<false><<<6250, 256>>>(src, dst, ew, yh, agg8);
    // 8: conv3 finalize
    fin3_kernel<<<(N_NODES + 127) / 128, 128>>>(x2, agg8, cinv, c3_rw, c3_lb, out);
}